// round 2
// baseline (speedup 1.0000x reference)
#include <cuda_runtime.h>
#include <math.h>

// Problem constants
#define BDIM 2
#define SEQ  2048
#define HID  2048
#define NH   8
#define HD   256
#define HALF 128

// SGEMM tiling
#define BM 128
#define BN 128
#define BKK 16
#define TM 8
#define TN 8

// Scratch (static device allocations — no cudaMalloc allowed)
__device__ float g_qraw[BDIM * SEQ * NH * HD];          // 33.5 MB
__device__ float g_kraw[BDIM * SEQ * HD];               // 4 MB
__device__ float g_q[BDIM * SEQ * NH * HD];             // 33.5 MB  [B,H,S,D]
__device__ float g_k[BDIM * SEQ * HD];                  // 4 MB     [B,S,D]
__device__ float g_v[BDIM * SEQ * HD];                  // 4 MB     [B,S,D]
__device__ float g_ah[BDIM * SEQ * NH * HD];            // 33.5 MB  [B,S,H*D]
__device__ float g_attn_scratch[(long long)BDIM * NH * SEQ * SEQ]; // 268 MB fallback

// ---------------------------------------------------------------------------
// NN SGEMM: C[M,N] = A[M,K] @ B[K,N], batched over blockIdx.z with generic
// per-z offsets: off = (z/zdiv)*outer + (z%zdiv)*inner for each of A,B,C.
// Optional causal K-limit: kmax = min(K, (m_tile+1)*BM).
// ---------------------------------------------------------------------------
__global__ __launch_bounds__(256) void sgemm_nn(
    const float* __restrict__ A, const float* __restrict__ Bm, float* __restrict__ C,
    int M, int N, int K, int lda, int ldb, int ldc,
    int zdiv, long long Ao, long long Ai, long long Bo, long long Bi,
    long long Co, long long Ci, int causal)
{
    __shared__ float As[BKK][BM];
    __shared__ float Bs[BKK][BN];

    int z = blockIdx.z;
    int zo = z / zdiv, zi = z - zo * zdiv;
    A  += zo * Ao + zi * Ai;
    Bm += zo * Bo + zi * Bi;
    C  += zo * Co + zi * Ci;

    int m0 = blockIdx.y * BM, n0 = blockIdx.x * BN;
    int tid = threadIdx.x;
    int tx = tid & 15, ty = tid >> 4;

    int kmax = causal ? min(K, (int)(blockIdx.y + 1) * BM) : K;

    float acc[TM][TN];
#pragma unroll
    for (int i = 0; i < TM; i++)
#pragma unroll
        for (int j = 0; j < TN; j++) acc[i][j] = 0.f;

    for (int k0 = 0; k0 < kmax; k0 += BKK) {
        // Load A tile [BM x BKK] -> As transposed [BKK][BM]
#pragma unroll
        for (int l = 0; l < 2; l++) {
            int s = tid * 2 + l;
            int r = s >> 2, c4 = (s & 3) * 4;
            float4 av = *(const float4*)(A + (long long)(m0 + r) * lda + k0 + c4);
            As[c4 + 0][r] = av.x; As[c4 + 1][r] = av.y;
            As[c4 + 2][r] = av.z; As[c4 + 3][r] = av.w;
        }
        // Load B tile [BKK x BN] -> Bs [BKK][BN]
#pragma unroll
        for (int l = 0; l < 2; l++) {
            int s = tid * 2 + l;
            int r = s >> 5, c4 = (s & 31) * 4;
            *(float4*)&Bs[r][c4] = *(const float4*)(Bm + (long long)(k0 + r) * ldb + n0 + c4);
        }
        __syncthreads();
#pragma unroll
        for (int kk = 0; kk < BKK; kk++) {
            float a[TM], b[TN];
#pragma unroll
            for (int i = 0; i < TM; i++) a[i] = As[kk][ty * TM + i];
#pragma unroll
            for (int j = 0; j < TN; j++) b[j] = Bs[kk][tx * TN + j];
#pragma unroll
            for (int i = 0; i < TM; i++)
#pragma unroll
                for (int j = 0; j < TN; j++) acc[i][j] += a[i] * b[j];
        }
        __syncthreads();
    }

#pragma unroll
    for (int i = 0; i < TM; i++) {
        float* cp = C + (long long)(m0 + ty * TM + i) * ldc + n0 + tx * TN;
        float4 v0 = make_float4(acc[i][0], acc[i][1], acc[i][2], acc[i][3]);
        float4 v1 = make_float4(acc[i][4], acc[i][5], acc[i][6], acc[i][7]);
        *(float4*)cp = v0;
        *(float4*)(cp + 4) = v1;
    }
}

// ---------------------------------------------------------------------------
// NT SGEMM: C[M,N] = A[M,K] @ B[N,K]^T (dot of rows). Causal tile skip:
// CTA (bx > by) is fully masked -> return (BM == BN).
// ---------------------------------------------------------------------------
__global__ __launch_bounds__(256) void sgemm_nt(
    const float* __restrict__ A, const float* __restrict__ Bm, float* __restrict__ C,
    int M, int N, int K, int lda, int ldb, int ldc,
    int zdiv, long long Ao, long long Ai, long long Bo, long long Bi,
    long long Co, long long Ci, int cskip)
{
    if (cskip && blockIdx.x > blockIdx.y) return;

    __shared__ float As[BKK][BM];
    __shared__ float Bs[BKK][BN];

    int z = blockIdx.z;
    int zo = z / zdiv, zi = z - zo * zdiv;
    A  += zo * Ao + zi * Ai;
    Bm += zo * Bo + zi * Bi;
    C  += zo * Co + zi * Ci;

    int m0 = blockIdx.y * BM, n0 = blockIdx.x * BN;
    int tid = threadIdx.x;
    int tx = tid & 15, ty = tid >> 4;

    float acc[TM][TN];
#pragma unroll
    for (int i = 0; i < TM; i++)
#pragma unroll
        for (int j = 0; j < TN; j++) acc[i][j] = 0.f;

    for (int k0 = 0; k0 < K; k0 += BKK) {
#pragma unroll
        for (int l = 0; l < 2; l++) {
            int s = tid * 2 + l;
            int r = s >> 2, c4 = (s & 3) * 4;
            float4 av = *(const float4*)(A + (long long)(m0 + r) * lda + k0 + c4);
            As[c4 + 0][r] = av.x; As[c4 + 1][r] = av.y;
            As[c4 + 2][r] = av.z; As[c4 + 3][r] = av.w;
        }
#pragma unroll
        for (int l = 0; l < 2; l++) {
            int s = tid * 2 + l;
            int r = s >> 2, c4 = (s & 3) * 4;   // r = n index, c4 = k offset
            float4 bv = *(const float4*)(Bm + (long long)(n0 + r) * ldb + k0 + c4);
            Bs[c4 + 0][r] = bv.x; Bs[c4 + 1][r] = bv.y;
            Bs[c4 + 2][r] = bv.z; Bs[c4 + 3][r] = bv.w;
        }
        __syncthreads();
#pragma unroll
        for (int kk = 0; kk < BKK; kk++) {
            float a[TM], b[TN];
#pragma unroll
            for (int i = 0; i < TM; i++) a[i] = As[kk][ty * TM + i];
#pragma unroll
            for (int j = 0; j < TN; j++) b[j] = Bs[kk][tx * TN + j];
#pragma unroll
            for (int i = 0; i < TM; i++)
#pragma unroll
                for (int j = 0; j < TN; j++) acc[i][j] += a[i] * b[j];
        }
        __syncthreads();
    }

#pragma unroll
    for (int i = 0; i < TM; i++) {
        float* cp = C + (long long)(m0 + ty * TM + i) * ldc + n0 + tx * TN;
        float4 v0 = make_float4(acc[i][0], acc[i][1], acc[i][2], acc[i][3]);
        float4 v1 = make_float4(acc[i][4], acc[i][5], acc[i][6], acc[i][7]);
        *(float4*)cp = v0;
        *(float4*)(cp + 4) = v1;
    }
}

// ---------------------------------------------------------------------------
// RoPE + q-scale. qraw [B,S,H,D] -> q [B,H,S,D] (scaled 1/16, roped);
// kraw [B,S,D]   -> k [B,S,D] (roped). One thread per (row, pair i).
// ---------------------------------------------------------------------------
__global__ void rope_kernel(const int* __restrict__ pos,
                            float* __restrict__ q, float* __restrict__ k)
{
    int t = blockIdx.x * 256 + threadIdx.x;
    const int TOT = BDIM * SEQ * (NH + 1) * HALF;
    if (t >= TOT) return;
    int i = t & (HALF - 1);
    int rest = t >> 7;
    int hh = rest % (NH + 1); rest /= (NH + 1);
    int s = rest % SEQ;
    int b = rest / SEQ;

    float p = (float)pos[b * SEQ + s];
    float freq = powf(10000.f, -(float)(2 * i) / (float)HD);
    float ang = p * freq;
    float sn, c;
    sincosf(ang, &sn, &c);

    if (hh < NH) {
        long long base = ((long long)(b * SEQ + s) * NH + hh) * HD;
        float x0 = g_qraw[base + i] * 0.0625f;
        float x1 = g_qraw[base + i + HALF] * 0.0625f;
        long long ob = ((long long)(b * NH + hh) * SEQ + s) * HD;
        q[ob + i]        = x0 * c - x1 * sn;
        q[ob + i + HALF] = x1 * c + x0 * sn;
    } else {
        long long base = (long long)(b * SEQ + s) * HD;
        float x0 = g_kraw[base + i];
        float x1 = g_kraw[base + i + HALF];
        k[base + i]        = x0 * c - x1 * sn;
        k[base + i + HALF] = x1 * c + x0 * sn;
    }
}

// ---------------------------------------------------------------------------
// Causal softmax in place: one block per row (b,h,q). Valid cols = q+1.
// Writes exact 0 for masked entries (matches exp(-1e9) == 0 in the reference).
// ---------------------------------------------------------------------------
__global__ __launch_bounds__(256) void softmax_causal(float* __restrict__ attn)
{
    __shared__ float sm[SEQ];
    __shared__ float red[256];
    long long row = blockIdx.x;
    int q = (int)(row % SEQ);
    float* r = attn + row * SEQ;
    int n = q + 1;
    int tid = threadIdx.x;

    float mx = -3.4e38f;
    for (int j = tid; j < n; j += 256) { float v = r[j]; sm[j] = v; mx = fmaxf(mx, v); }
    red[tid] = mx; __syncthreads();
    for (int s = 128; s > 0; s >>= 1) { if (tid < s) red[tid] = fmaxf(red[tid], red[tid + s]); __syncthreads(); }
    mx = red[0];
    __syncthreads();

    float sum = 0.f;
    for (int j = tid; j < n; j += 256) { float e = expf(sm[j] - mx); sm[j] = e; sum += e; }
    red[tid] = sum; __syncthreads();
    for (int s = 128; s > 0; s >>= 1) { if (tid < s) red[tid] += red[tid + s]; __syncthreads(); }
    float inv = 1.f / red[0];

    for (int j = tid; j < SEQ; j += 256) r[j] = (j < n) ? sm[j] * inv : 0.f;
}

// ---------------------------------------------------------------------------
// Host launcher
// ---------------------------------------------------------------------------
extern "C" void kernel_launch(void* const* d_in, const int* in_sizes, int n_in,
                              void* d_out, int out_size)
{
    const float* hidden = (const float*)d_in[0];
    const float* Wq     = (const float*)d_in[1];
    const float* Wk     = (const float*)d_in[2];
    const float* Wv     = (const float*)d_in[3];
    const float* Wo     = (const float*)d_in[4];
    const int*   pos    = (const int*)d_in[6];

    float *qraw, *kraw, *q, *k, *v, *ah, *attn_s;
    cudaGetSymbolAddress((void**)&qraw,   g_qraw);
    cudaGetSymbolAddress((void**)&kraw,   g_kraw);
    cudaGetSymbolAddress((void**)&q,      g_q);
    cudaGetSymbolAddress((void**)&k,      g_k);
    cudaGetSymbolAddress((void**)&v,      g_v);
    cudaGetSymbolAddress((void**)&ah,     g_ah);
    cudaGetSymbolAddress((void**)&attn_s, g_attn_scratch);

    float* out = (float*)d_out;
    const long long OUTE  = (long long)BDIM * SEQ * HID;                 // 8388608
    const long long ATTNE = (long long)BDIM * NH * SEQ * SEQ;            // 67108864
    float* attn = ((long long)out_size >= OUTE + ATTNE) ? (out + OUTE) : attn_s;

    dim3 t(256);
    const int M = BDIM * SEQ; // 4096

    // 1-3: projections (hidden [4096,2048] @ W)
    sgemm_nn<<<dim3(HID / BN, M / BM, 1), t>>>(hidden, Wq, qraw,
        M, HID, HID, HID, HID, HID, 1, 0, 0, 0, 0, 0, 0, 0);
    sgemm_nn<<<dim3(HD / BN, M / BM, 1), t>>>(hidden, Wk, kraw,
        M, HD, HID, HID, HD, HD, 1, 0, 0, 0, 0, 0, 0, 0);
    sgemm_nn<<<dim3(HD / BN, M / BM, 1), t>>>(hidden, Wv, v,
        M, HD, HID, HID, HD, HD, 1, 0, 0, 0, 0, 0, 0, 0);

    // 4: scale + RoPE + layout transform
    {
        int TOT = BDIM * SEQ * (NH + 1) * HALF;
        rope_kernel<<<(TOT + 255) / 256, 256>>>(pos, q, k);
    }

    // 5: scores = q @ k^T per (b,h), causal tile skip
    sgemm_nt<<<dim3(SEQ / BN, SEQ / BM, BDIM * NH), t>>>(q, k, attn,
        SEQ, SEQ, HD, HD, HD, SEQ,
        NH,
        (long long)NH * SEQ * HD, (long long)SEQ * HD,   // A: q [B,H,S,D]
        (long long)SEQ * HD, 0,                          // B: k [B,S,D]
        (long long)NH * SEQ * SEQ, (long long)SEQ * SEQ, // C: attn [B,H,S,S]
        1);

    // 6: softmax (writes full attn output, zeros in masked region)
    softmax_causal<<<BDIM * NH * SEQ, 256>>>(attn);

    // 7: PV: out_heads = attn @ v, written to [B,S,H*D] layout, causal K-limit
    sgemm_nn<<<dim3(HD / BN, SEQ / BM, BDIM * NH), t>>>(attn, v, ah,
        SEQ, HD, SEQ, SEQ, HD, NH * HD,
        NH,
        (long long)NH * SEQ * SEQ, (long long)SEQ * SEQ, // A: attn
        (long long)SEQ * HD, 0,                          // B: v [B,S,D]
        (long long)SEQ * NH * HD, (long long)HD,         // C: ah [B,S,H*D] (+h*D)
        1);

    // 8: out = ah @ Wo
    sgemm_nn<<<dim3(HID / BN, M / BM, 1), t>>>(ah, Wo, out,
        M, HID, NH * HD, NH * HD, HID, HID, 1, 0, 0, 0, 0, 0, 0, 0);
}

// round 4
// speedup vs baseline: 1.9861x; 1.9861x over previous
#include <cuda_runtime.h>
#include <cuda_bf16.h>
#include <math.h>
#include <stdint.h>

#define BDIM 2
#define SEQ  2048
#define HID  2048
#define NH   8
#define HD   256
#define HALF 128

#define BM 128
#define BN 128
#define BK 32

typedef __nv_bfloat16 bf16;

// ------------------------- static device scratch ---------------------------
__device__ __align__(16) float g_qraw[BDIM*SEQ*NH*HD];
__device__ __align__(16) float g_kraw[BDIM*SEQ*HD];
__device__ __align__(16) float g_v   [BDIM*SEQ*HD];
__device__ __align__(16) float g_ah  [BDIM*SEQ*NH*HD];
__device__ __align__(16) float g_attn_s[(size_t)BDIM*NH*SEQ*SEQ];

__device__ __align__(16) bf16 g_hid_h[BDIM*SEQ*HID], g_hid_l[BDIM*SEQ*HID];
__device__ __align__(16) bf16 g_wq_h[HID*NH*HD],     g_wq_l[HID*NH*HD];
__device__ __align__(16) bf16 g_wk_h[HID*HD],        g_wk_l[HID*HD];
__device__ __align__(16) bf16 g_wv_h[HID*HD],        g_wv_l[HID*HD];
__device__ __align__(16) bf16 g_wo_h[NH*HD*HID],     g_wo_l[NH*HD*HID];
__device__ __align__(16) bf16 g_q_h[BDIM*NH*SEQ*HD], g_q_l[BDIM*NH*SEQ*HD];
__device__ __align__(16) bf16 g_k_h[BDIM*SEQ*HD],    g_k_l[BDIM*SEQ*HD];
__device__ __align__(16) bf16 g_v_h[BDIM*SEQ*HD],    g_v_l[BDIM*SEQ*HD];
__device__ __align__(16) bf16 g_ah_h[BDIM*SEQ*NH*HD],g_ah_l[BDIM*SEQ*NH*HD];
__device__ __align__(16) bf16 g_at_h[(size_t)BDIM*NH*SEQ*SEQ];
__device__ __align__(16) bf16 g_at_l[(size_t)BDIM*NH*SEQ*SEQ];

// ------------------------------- helpers -----------------------------------
__device__ __forceinline__ uint32_t smem_u32(const void* p) {
    return (uint32_t)__cvta_generic_to_shared(p);
}

__device__ __forceinline__ void ldm4(uint32_t r[4], uint32_t a) {
    asm volatile("ldmatrix.sync.aligned.m8n8.x4.shared.b16 {%0,%1,%2,%3}, [%4];\n"
                 : "=r"(r[0]), "=r"(r[1]), "=r"(r[2]), "=r"(r[3]) : "r"(a));
}
__device__ __forceinline__ void ldm4t(uint32_t r[4], uint32_t a) {
    asm volatile("ldmatrix.sync.aligned.m8n8.x4.trans.shared.b16 {%0,%1,%2,%3}, [%4];\n"
                 : "=r"(r[0]), "=r"(r[1]), "=r"(r[2]), "=r"(r[3]) : "r"(a));
}
__device__ __forceinline__ void mma_bf16(float c[4], const uint32_t a[4],
                                         uint32_t b0, uint32_t b1) {
    asm volatile(
        "mma.sync.aligned.m16n8k16.row.col.f32.bf16.bf16.f32 "
        "{%0,%1,%2,%3}, {%4,%5,%6,%7}, {%8,%9}, {%0,%1,%2,%3};\n"
        : "+f"(c[0]), "+f"(c[1]), "+f"(c[2]), "+f"(c[3])
        : "r"(a[0]), "r"(a[1]), "r"(a[2]), "r"(a[3]), "r"(b0), "r"(b1));
}

// ---------------------------------------------------------------------------
// Split-bf16 GEMM. C[M,N](f32) += (Ah+Al)(Bh+Bl) via 3 bf16 MMA passes.
// NT=false: B is [K,N] row-major (NN). NT=true: B is [N,K] row-major (C=A·B^T).
// Batched over blockIdx.z: off = (z/zdiv)*Xo + (z%zdiv)*Xi.
// cmode: 0 none; 1 (NT) causal tile-skip; 2 (NN) causal k-limit.
// 256 threads, warp grid 2(m) x 4(n), warp tile 64x32.
// ---------------------------------------------------------------------------
template<bool NT>
__global__ __launch_bounds__(256, 1) void gemm_split(
    const bf16* __restrict__ Ah, const bf16* __restrict__ Al,
    const bf16* __restrict__ Bh, const bf16* __restrict__ Bl,
    float* __restrict__ C,
    int K, int lda, int ldb, int ldc,
    int zdiv, long long Ao, long long Ai, long long Bo, long long Bi,
    long long Co, long long Ci, int cmode)
{
    if (NT && cmode == 1 && blockIdx.x > blockIdx.y) return;

    constexpr int ASTR  = BK + 8;                 // 40 bf16 (80B, conflict-free ldmatrix)
    constexpr int BROWS = NT ? BN : BK;
    constexpr int BSTR  = NT ? (BK + 8) : (BN + 8);
    __shared__ bf16 sAh[BM][ASTR],   sAl[BM][ASTR];
    __shared__ bf16 sBh[BROWS][BSTR], sBl[BROWS][BSTR];

    int z = blockIdx.z;
    int zo = z / zdiv, zi = z - zo * zdiv;
    Ah += zo * Ao + zi * Ai;  Al += zo * Ao + zi * Ai;
    Bh += zo * Bo + zi * Bi;  Bl += zo * Bo + zi * Bi;
    C  += zo * Co + zi * Ci;

    int m0 = blockIdx.y * BM, n0 = blockIdx.x * BN;
    int tid = threadIdx.x, lane = tid & 31, wid = tid >> 5;
    int wm = wid & 1, wn = wid >> 1;

    int kmax = (!NT && cmode == 2) ? min(K, (int)(blockIdx.y + 1) * BM) : K;

    float c[4][4][4];
#pragma unroll
    for (int mt = 0; mt < 4; mt++)
#pragma unroll
        for (int nt = 0; nt < 4; nt++)
#pragma unroll
            for (int i = 0; i < 4; i++) c[mt][nt][i] = 0.f;

    // A-tile (and NT B-tile) quad indices: 128x32 tile, 2 quads/thread
    const int ar0 = tid >> 2,          ac0 = (tid & 3) * 8;
    const int ar1 = (tid + 256) >> 2,  ac1 = (tid & 3) * 8;   // (tid+256)&3 == tid&3
    // NN B-tile: 32x128, 2 quads/thread
    const int br0 = tid >> 4,          bc0 = (tid & 15) * 8;
    const int br1 = (tid + 256) >> 4,  bc1 = (tid & 15) * 8;

    for (int k0 = 0; k0 < kmax; k0 += BK) {
        uint4 rah0, rah1, ral0, ral1, rbh0, rbh1, rbl0, rbl1;
        // ---- gmem -> regs ----
        rah0 = *(const uint4*)(Ah + (size_t)(m0 + ar0) * lda + k0 + ac0);
        rah1 = *(const uint4*)(Ah + (size_t)(m0 + ar1) * lda + k0 + ac1);
        ral0 = *(const uint4*)(Al + (size_t)(m0 + ar0) * lda + k0 + ac0);
        ral1 = *(const uint4*)(Al + (size_t)(m0 + ar1) * lda + k0 + ac1);
        if (NT) {
            rbh0 = *(const uint4*)(Bh + (size_t)(n0 + ar0) * ldb + k0 + ac0);
            rbh1 = *(const uint4*)(Bh + (size_t)(n0 + ar1) * ldb + k0 + ac1);
            rbl0 = *(const uint4*)(Bl + (size_t)(n0 + ar0) * ldb + k0 + ac0);
            rbl1 = *(const uint4*)(Bl + (size_t)(n0 + ar1) * ldb + k0 + ac1);
        } else {
            rbh0 = *(const uint4*)(Bh + (size_t)(k0 + br0) * ldb + n0 + bc0);
            rbh1 = *(const uint4*)(Bh + (size_t)(k0 + br1) * ldb + n0 + bc1);
            rbl0 = *(const uint4*)(Bl + (size_t)(k0 + br0) * ldb + n0 + bc0);
            rbl1 = *(const uint4*)(Bl + (size_t)(k0 + br1) * ldb + n0 + bc1);
        }
        __syncthreads();   // previous iteration's compute done
        // ---- regs -> smem ----
        *(uint4*)&sAh[ar0][ac0] = rah0;  *(uint4*)&sAh[ar1][ac1] = rah1;
        *(uint4*)&sAl[ar0][ac0] = ral0;  *(uint4*)&sAl[ar1][ac1] = ral1;
        if (NT) {
            *(uint4*)&sBh[ar0][ac0] = rbh0;  *(uint4*)&sBh[ar1][ac1] = rbh1;
            *(uint4*)&sBl[ar0][ac0] = rbl0;  *(uint4*)&sBl[ar1][ac1] = rbl1;
        } else {
            *(uint4*)&sBh[br0][bc0] = rbh0;  *(uint4*)&sBh[br1][bc1] = rbh1;
            *(uint4*)&sBl[br0][bc0] = rbl0;  *(uint4*)&sBl[br1][bc1] = rbl1;
        }
        __syncthreads();

        // ---- compute: 2 k-steps of 16 ----
#pragma unroll
        for (int ks = 0; ks < BK; ks += 16) {
            uint32_t fah[4][4], fal[4][4];
#pragma unroll
            for (int mt = 0; mt < 4; mt++) {
                int row = wm * 64 + mt * 16 + (lane & 15);
                int col = ks + ((lane >> 4) << 3);
                ldm4(fah[mt], smem_u32(&sAh[row][col]));
                ldm4(fal[mt], smem_u32(&sAl[row][col]));
            }
            uint32_t fbh[8], fbl[8];
#pragma unroll
            for (int p = 0; p < 2; p++) {
                if (NT) {
                    int row = wn * 32 + p * 16 + (lane & 7) + ((lane >> 4) << 3);
                    int col = ks + (lane & 8);
                    ldm4(&fbh[4 * p], smem_u32(&sBh[row][col]));
                    ldm4(&fbl[4 * p], smem_u32(&sBl[row][col]));
                } else {
                    int row = ks + (lane & 15);
                    int col = wn * 32 + p * 16 + ((lane >> 4) << 3);
                    ldm4t(&fbh[4 * p], smem_u32(&sBh[row][col]));
                    ldm4t(&fbl[4 * p], smem_u32(&sBl[row][col]));
                }
            }
#pragma unroll
            for (int mt = 0; mt < 4; mt++)
#pragma unroll
                for (int nt = 0; nt < 4; nt++) {
                    mma_bf16(c[mt][nt], fah[mt], fbh[2*nt], fbh[2*nt+1]);
                    mma_bf16(c[mt][nt], fah[mt], fbl[2*nt], fbl[2*nt+1]);
                    mma_bf16(c[mt][nt], fal[mt], fbh[2*nt], fbh[2*nt+1]);
                }
        }
    }

    // ---- epilogue ----
#pragma unroll
    for (int mt = 0; mt < 4; mt++)
#pragma unroll
        for (int nt = 0; nt < 4; nt++) {
            int row = m0 + wm * 64 + mt * 16 + (lane >> 2);
            int col = n0 + wn * 32 + nt * 8 + (lane & 3) * 2;
            float2 v0 = make_float2(c[mt][nt][0], c[mt][nt][1]);
            float2 v1 = make_float2(c[mt][nt][2], c[mt][nt][3]);
            *(float2*)(C + (size_t)row * ldc + col)       = v0;
            *(float2*)(C + (size_t)(row + 8) * ldc + col) = v1;
        }
}

// ---------------------------------------------------------------------------
// fp32 -> (hi, lo) bf16 planes
// ---------------------------------------------------------------------------
__global__ void split_fp32(const float* __restrict__ x,
                           bf16* __restrict__ h, bf16* __restrict__ l, int n)
{
    int i = blockIdx.x * 256 + threadIdx.x;
    if (i >= n) return;
    float v = x[i];
    bf16 hb = __float2bfloat16(v);
    h[i] = hb;
    l[i] = __float2bfloat16(v - __bfloat162float(hb));
}

// ---------------------------------------------------------------------------
// RoPE + q scale; qraw [B,S,H,D] -> q planes [B,H,S,D]; kraw [B,S,D] -> k planes
// ---------------------------------------------------------------------------
__global__ void rope_split(const int* __restrict__ pos,
                           bf16* __restrict__ qh, bf16* __restrict__ ql,
                           bf16* __restrict__ kh, bf16* __restrict__ kl)
{
    int t = blockIdx.x * 256 + threadIdx.x;
    const int TOT = BDIM * SEQ * (NH + 1) * HALF;
    if (t >= TOT) return;
    int i = t & (HALF - 1);
    int rest = t >> 7;
    int hh = rest % (NH + 1); rest /= (NH + 1);
    int s = rest % SEQ;
    int b = rest / SEQ;

    float p = (float)pos[b * SEQ + s];
    float freq = powf(10000.f, -(float)(2 * i) / (float)HD);
    float ang = p * freq;
    float sn, cs;
    sincosf(ang, &sn, &cs);

    float y0, y1;
    size_t ob;
    if (hh < NH) {
        size_t base = ((size_t)(b * SEQ + s) * NH + hh) * HD;
        float x0 = g_qraw[base + i] * 0.0625f;
        float x1 = g_qraw[base + i + HALF] * 0.0625f;
        y0 = x0 * cs - x1 * sn;
        y1 = x1 * cs + x0 * sn;
        ob = ((size_t)(b * NH + hh) * SEQ + s) * HD;
        bf16 h0 = __float2bfloat16(y0);
        qh[ob + i] = h0; ql[ob + i] = __float2bfloat16(y0 - __bfloat162float(h0));
        bf16 h1 = __float2bfloat16(y1);
        qh[ob + i + HALF] = h1; ql[ob + i + HALF] = __float2bfloat16(y1 - __bfloat162float(h1));
    } else {
        size_t base = (size_t)(b * SEQ + s) * HD;
        float x0 = g_kraw[base + i];
        float x1 = g_kraw[base + i + HALF];
        y0 = x0 * cs - x1 * sn;
        y1 = x1 * cs + x0 * sn;
        bf16 h0 = __float2bfloat16(y0);
        kh[base + i] = h0; kl[base + i] = __float2bfloat16(y0 - __bfloat162float(h0));
        bf16 h1 = __float2bfloat16(y1);
        kh[base + i + HALF] = h1; kl[base + i + HALF] = __float2bfloat16(y1 - __bfloat162float(h1));
    }
}

// ---------------------------------------------------------------------------
// Causal softmax in place + bf16 hi/lo planes for the PV GEMM.
// ---------------------------------------------------------------------------
__global__ __launch_bounds__(256) void softmax_causal_split(
    float* __restrict__ attn, bf16* __restrict__ ah, bf16* __restrict__ al)
{
    __shared__ float sm[SEQ];
    __shared__ float red[256];
    size_t row = blockIdx.x;
    int q = (int)(row % SEQ);
    float* r  = attn + row * SEQ;
    bf16*  rh = ah   + row * SEQ;
    bf16*  rl = al   + row * SEQ;
    int n = q + 1;
    int tid = threadIdx.x;

    float mx = -3.4e38f;
    for (int j = tid; j < n; j += 256) { float v = r[j]; sm[j] = v; mx = fmaxf(mx, v); }
    red[tid] = mx; __syncthreads();
    for (int s = 128; s > 0; s >>= 1) { if (tid < s) red[tid] = fmaxf(red[tid], red[tid + s]); __syncthreads(); }
    mx = red[0];
    __syncthreads();

    float sum = 0.f;
    for (int j = tid; j < n; j += 256) { float e = expf(sm[j] - mx); sm[j] = e; sum += e; }
    red[tid] = sum; __syncthreads();
    for (int s = 128; s > 0; s >>= 1) { if (tid < s) red[tid] += red[tid + s]; __syncthreads(); }
    float inv = 1.f / red[0];

    for (int j = tid; j < SEQ; j += 256) {
        float o = (j < n) ? sm[j] * inv : 0.f;
        r[j] = o;
        bf16 hb = __float2bfloat16(o);
        rh[j] = hb;
        rl[j] = __float2bfloat16(o - __bfloat162float(hb));
    }
}

// ---------------------------------------------------------------------------
// Host launcher
// ---------------------------------------------------------------------------
extern "C" void kernel_launch(void* const* d_in, const int* in_sizes, int n_in,
                              void* d_out, int out_size)
{
    const float* hidden = (const float*)d_in[0];
    const float* Wq     = (const float*)d_in[1];
    const float* Wk     = (const float*)d_in[2];
    const float* Wv     = (const float*)d_in[3];
    const float* Wo     = (const float*)d_in[4];
    const int*   pos    = (const int*)d_in[6];

    float *qraw, *kraw, *v, *ahf, *attn_s;
    bf16 *hid_h, *hid_l, *wq_h, *wq_l, *wk_h, *wk_l, *wv_h, *wv_l, *wo_h, *wo_l;
    bf16 *q_h, *q_l, *k_h, *k_l, *v_h, *v_l, *ah_h, *ah_l, *at_h, *at_l;

    cudaGetSymbolAddress((void**)&qraw, g_qraw);
    cudaGetSymbolAddress((void**)&kraw, g_kraw);
    cudaGetSymbolAddress((void**)&v,    g_v);
    cudaGetSymbolAddress((void**)&ahf,  g_ah);
    cudaGetSymbolAddress((void**)&attn_s, g_attn_s);
    cudaGetSymbolAddress((void**)&hid_h, g_hid_h); cudaGetSymbolAddress((void**)&hid_l, g_hid_l);
    cudaGetSymbolAddress((void**)&wq_h, g_wq_h);   cudaGetSymbolAddress((void**)&wq_l, g_wq_l);
    cudaGetSymbolAddress((void**)&wk_h, g_wk_h);   cudaGetSymbolAddress((void**)&wk_l, g_wk_l);
    cudaGetSymbolAddress((void**)&wv_h, g_wv_h);   cudaGetSymbolAddress((void**)&wv_l, g_wv_l);
    cudaGetSymbolAddress((void**)&wo_h, g_wo_h);   cudaGetSymbolAddress((void**)&wo_l, g_wo_l);
    cudaGetSymbolAddress((void**)&q_h, g_q_h);     cudaGetSymbolAddress((void**)&q_l, g_q_l);
    cudaGetSymbolAddress((void**)&k_h, g_k_h);     cudaGetSymbolAddress((void**)&k_l, g_k_l);
    cudaGetSymbolAddress((void**)&v_h, g_v_h);     cudaGetSymbolAddress((void**)&v_l, g_v_l);
    cudaGetSymbolAddress((void**)&ah_h, g_ah_h);   cudaGetSymbolAddress((void**)&ah_l, g_ah_l);
    cudaGetSymbolAddress((void**)&at_h, g_at_h);   cudaGetSymbolAddress((void**)&at_l, g_at_l);

    float* out = (float*)d_out;
    const long long OUTE  = (long long)BDIM * SEQ * HID;
    const long long ATTNE = (long long)BDIM * NH * SEQ * SEQ;
    float* attn = ((long long)out_size >= OUTE + ATTNE) ? (out + OUTE) : attn_s;

    const int M = BDIM * SEQ;  // 4096

    // splits of inputs
    { int n = BDIM*SEQ*HID;  split_fp32<<<n/256, 256>>>(hidden, hid_h, hid_l, n); }
    { int n = HID*NH*HD;     split_fp32<<<n/256, 256>>>(Wq, wq_h, wq_l, n); }
    { int n = HID*HD;        split_fp32<<<n/256, 256>>>(Wk, wk_h, wk_l, n); }
    { int n = HID*HD;        split_fp32<<<n/256, 256>>>(Wv, wv_h, wv_l, n); }
    { int n = NH*HD*HID;     split_fp32<<<n/256, 256>>>(Wo, wo_h, wo_l, n); }

    // projections
    gemm_split<false><<<dim3(HID/BN, M/BM, 1), 256>>>(hid_h, hid_l, wq_h, wq_l, qraw,
        HID, HID, HID, HID, 1, 0,0,0,0,0,0, 0);
    gemm_split<false><<<dim3(HD/BN, M/BM, 1), 256>>>(hid_h, hid_l, wk_h, wk_l, kraw,
        HID, HID, HD, HD, 1, 0,0,0,0,0,0, 0);
    gemm_split<false><<<dim3(HD/BN, M/BM, 1), 256>>>(hid_h, hid_l, wv_h, wv_l, v,
        HID, HID, HD, HD, 1, 0,0,0,0,0,0, 0);

    { int n = BDIM*SEQ*HD; split_fp32<<<n/256, 256>>>(v, v_h, v_l, n); }

    // RoPE + split q/k
    { int TOT = BDIM*SEQ*(NH+1)*HALF; rope_split<<<(TOT+255)/256, 256>>>(pos, q_h, q_l, k_h, k_l); }

    // scores = q @ k^T (NT), causal tile skip
    gemm_split<true><<<dim3(SEQ/BN, SEQ/BM, BDIM*NH), 256>>>(q_h, q_l, k_h, k_l, attn,
        HD, HD, HD, SEQ,
        NH,
        (long long)NH*SEQ*HD, (long long)SEQ*HD,
        (long long)SEQ*HD, 0,
        (long long)NH*SEQ*SEQ, (long long)SEQ*SEQ,
        1);

    // softmax + attn split
    softmax_causal_split<<<BDIM*NH*SEQ, 256>>>(attn, at_h, at_l);

    // PV: ah = attn @ v -> [B,S,H*D], causal k-limit
    gemm_split<false><<<dim3(HD/BN, SEQ/BM, BDIM*NH), 256>>>(at_h, at_l, v_h, v_l, ahf,
        SEQ, SEQ, HD, NH*HD,
        NH,
        (long long)NH*SEQ*SEQ, (long long)SEQ*SEQ,
        (long long)SEQ*HD, 0,
        (long long)SEQ*NH*HD, (long long)HD,
        2);

    { int n = BDIM*SEQ*NH*HD; split_fp32<<<n/256, 256>>>(ahf, ah_h, ah_l, n); }

    // out = ah @ Wo
    gemm_split<false><<<dim3(HID/BN, M/BM, 1), 256>>>(ah_h, ah_l, wo_h, wo_l, out,
        NH*HD, NH*HD, HID, HID, 1, 0,0,0,0,0,0, 0);
}

// round 5
// speedup vs baseline: 2.4212x; 1.2191x over previous
#include <cuda_runtime.h>
#include <cuda_bf16.h>
#include <math.h>
#include <stdint.h>

#define BDIM 2
#define SEQ  2048
#define HID  2048
#define NH   8
#define HD   256
#define HALF 128

#define BM 128
#define BN 128
#define BK 32
#define STAGES 3

typedef __nv_bfloat16 bf16;

// ------------------------- static device scratch ---------------------------
__device__ __align__(16) float g_qraw[BDIM*SEQ*NH*HD];
__device__ __align__(16) float g_kraw[BDIM*SEQ*HD];
__device__ __align__(16) float g_attn_s[(size_t)BDIM*NH*SEQ*SEQ];

__device__ __align__(16) bf16 g_hid_h[BDIM*SEQ*HID], g_hid_l[BDIM*SEQ*HID];
__device__ __align__(16) bf16 g_wq_h[HID*NH*HD],     g_wq_l[HID*NH*HD];
__device__ __align__(16) bf16 g_wk_h[HID*HD],        g_wk_l[HID*HD];
__device__ __align__(16) bf16 g_wv_h[HID*HD],        g_wv_l[HID*HD];
__device__ __align__(16) bf16 g_wo_h[NH*HD*HID],     g_wo_l[NH*HD*HID];
__device__ __align__(16) bf16 g_q_h[BDIM*NH*SEQ*HD], g_q_l[BDIM*NH*SEQ*HD];
__device__ __align__(16) bf16 g_k_h[BDIM*SEQ*HD],    g_k_l[BDIM*SEQ*HD];
__device__ __align__(16) bf16 g_v_h[BDIM*SEQ*HD],    g_v_l[BDIM*SEQ*HD];
__device__ __align__(16) bf16 g_ah_h[BDIM*SEQ*NH*HD],g_ah_l[BDIM*SEQ*NH*HD];
__device__ __align__(16) bf16 g_at_h[(size_t)BDIM*NH*SEQ*SEQ];
__device__ __align__(16) bf16 g_at_l[(size_t)BDIM*NH*SEQ*SEQ];

// ------------------------------- helpers -----------------------------------
__device__ __forceinline__ uint32_t smem_u32(const void* p) {
    return (uint32_t)__cvta_generic_to_shared(p);
}
__device__ __forceinline__ void cp16(void* dst, const void* src) {
    asm volatile("cp.async.cg.shared.global [%0], [%1], 16;\n"
                 :: "r"(smem_u32(dst)), "l"(src));
}
__device__ __forceinline__ void cp_commit() {
    asm volatile("cp.async.commit_group;\n");
}
template<int N> __device__ __forceinline__ void cp_wait() {
    asm volatile("cp.async.wait_group %0;\n" :: "n"(N));
}
__device__ __forceinline__ void ldm4(uint32_t r[4], uint32_t a) {
    asm volatile("ldmatrix.sync.aligned.m8n8.x4.shared.b16 {%0,%1,%2,%3}, [%4];\n"
                 : "=r"(r[0]), "=r"(r[1]), "=r"(r[2]), "=r"(r[3]) : "r"(a));
}
__device__ __forceinline__ void ldm4t(uint32_t r[4], uint32_t a) {
    asm volatile("ldmatrix.sync.aligned.m8n8.x4.trans.shared.b16 {%0,%1,%2,%3}, [%4];\n"
                 : "=r"(r[0]), "=r"(r[1]), "=r"(r[2]), "=r"(r[3]) : "r"(a));
}
__device__ __forceinline__ void mma_bf16(float c[4], const uint32_t a[4],
                                         uint32_t b0, uint32_t b1) {
    asm volatile(
        "mma.sync.aligned.m16n8k16.row.col.f32.bf16.bf16.f32 "
        "{%0,%1,%2,%3}, {%4,%5,%6,%7}, {%8,%9}, {%0,%1,%2,%3};\n"
        : "+f"(c[0]), "+f"(c[1]), "+f"(c[2]), "+f"(c[3])
        : "r"(a[0]), "r"(a[1]), "r"(a[2]), "r"(a[3]), "r"(b0), "r"(b1));
}
__device__ __forceinline__ uint32_t pack2bf(float a, float b) {
    __nv_bfloat162 v;
    v.x = __float2bfloat16(a); v.y = __float2bfloat16(b);
    return *(uint32_t*)&v;
}

// ---------------------------------------------------------------------------
// Split-bf16 GEMM, 3-stage cp.async pipeline.
// C += (Ah+Al)(Bh+Bl) via 3 bf16 MMA passes (hh + hl + lh).
// NT=false: B [K,N] row-major.  NT=true: B [N,K] row-major (C = A·B^T).
// Outputs: C (f32, optional) and Ch/Cl (bf16 hi/lo planes, optional).
// Batched over blockIdx.z: off = (z/zdiv)*Xo + (z%zdiv)*Xi.
// cmode: 0 none; 1 (NT) causal tile-skip; 2 (NN) causal K-limit.
// 256 threads, warps 2(m) x 4(n), warp tile 64x32.
// ---------------------------------------------------------------------------
template<bool NT>
__global__ __launch_bounds__(256, 1) void gemm_split(
    const bf16* __restrict__ Ah, const bf16* __restrict__ Al,
    const bf16* __restrict__ Bh, const bf16* __restrict__ Bl,
    float* __restrict__ C, bf16* __restrict__ Ch, bf16* __restrict__ Cl,
    int K, int lda, int ldb, int ldc,
    int zdiv, long long Ao, long long Ai, long long Bo, long long Bi,
    long long Co, long long Ci, int cmode)
{
    if (NT && cmode == 1 && blockIdx.x > blockIdx.y) return;

    constexpr int ASTR  = BK + 8;                  // 40 bf16 rows (80B, 16B-aligned)
    constexpr int BROWS = NT ? BN : BK;
    constexpr int BSTR  = NT ? (BK + 8) : (BN + 8);
    constexpr int AELEM = BM * ASTR;
    constexpr int BELEM = BROWS * BSTR;

    extern __shared__ bf16 smem[];
    bf16* pAh = smem;
    bf16* pAl = pAh + STAGES * AELEM;
    bf16* pBh = pAl + STAGES * AELEM;
    bf16* pBl = pBh + STAGES * BELEM;

    int z = blockIdx.z;
    int zo = z / zdiv, zi = z - zo * zdiv;
    Ah += zo * Ao + zi * Ai;  Al += zo * Ao + zi * Ai;
    Bh += zo * Bo + zi * Bi;  Bl += zo * Bo + zi * Bi;
    long long coff = zo * Co + zi * Ci;

    int m0 = blockIdx.y * BM, n0 = blockIdx.x * BN;
    int tid = threadIdx.x, lane = tid & 31, wid = tid >> 5;
    int wm = wid & 1, wn = wid >> 1;

    int kmax = (!NT && cmode == 2) ? min(K, (int)(blockIdx.y + 1) * BM) : K;
    int niter = kmax / BK;

    // per-thread load slots
    const int ar0 = tid >> 2,         ac0 = (tid & 3) * 8;
    const int ar1 = (tid + 256) >> 2, ac1 = ac0;
    const int br0 = tid >> 4,         bc0 = (tid & 15) * 8;
    const int br1 = (tid + 256) >> 4, bc1 = bc0;

    float c[4][4][4];
#pragma unroll
    for (int mt = 0; mt < 4; mt++)
#pragma unroll
        for (int nt = 0; nt < 4; nt++)
#pragma unroll
            for (int i = 0; i < 4; i++) c[mt][nt][i] = 0.f;

    auto load_stage = [&](int st, int k0) {
        bf16* ah = pAh + st * AELEM;  bf16* al = pAl + st * AELEM;
        bf16* bh = pBh + st * BELEM;  bf16* bl = pBl + st * BELEM;
        cp16(ah + ar0 * ASTR + ac0, Ah + (size_t)(m0 + ar0) * lda + k0 + ac0);
        cp16(ah + ar1 * ASTR + ac1, Ah + (size_t)(m0 + ar1) * lda + k0 + ac1);
        cp16(al + ar0 * ASTR + ac0, Al + (size_t)(m0 + ar0) * lda + k0 + ac0);
        cp16(al + ar1 * ASTR + ac1, Al + (size_t)(m0 + ar1) * lda + k0 + ac1);
        if (NT) {
            cp16(bh + ar0 * BSTR + ac0, Bh + (size_t)(n0 + ar0) * ldb + k0 + ac0);
            cp16(bh + ar1 * BSTR + ac1, Bh + (size_t)(n0 + ar1) * ldb + k0 + ac1);
            cp16(bl + ar0 * BSTR + ac0, Bl + (size_t)(n0 + ar0) * ldb + k0 + ac0);
            cp16(bl + ar1 * BSTR + ac1, Bl + (size_t)(n0 + ar1) * ldb + k0 + ac1);
        } else {
            cp16(bh + br0 * BSTR + bc0, Bh + (size_t)(k0 + br0) * ldb + n0 + bc0);
            cp16(bh + br1 * BSTR + bc1, Bh + (size_t)(k0 + br1) * ldb + n0 + bc1);
            cp16(bl + br0 * BSTR + bc0, Bl + (size_t)(k0 + br0) * ldb + n0 + bc0);
            cp16(bl + br1 * BSTR + bc1, Bl + (size_t)(k0 + br1) * ldb + n0 + bc1);
        }
    };

    // prologue: preload STAGES-1 stages (commit each, even if empty)
#pragma unroll
    for (int s = 0; s < STAGES - 1; s++) {
        if (s < niter) load_stage(s, s * BK);
        cp_commit();
    }

    for (int it = 0; it < niter; it++) {
        cp_wait<STAGES - 2>();
        __syncthreads();

        // prefetch stage it+STAGES-1
        int nk = it + STAGES - 1;
        if (nk < niter) load_stage(nk % STAGES, nk * BK);
        cp_commit();

        int st = it % STAGES;
        const bf16* ah = pAh + st * AELEM;  const bf16* al = pAl + st * AELEM;
        const bf16* bh = pBh + st * BELEM;  const bf16* bl = pBl + st * BELEM;

#pragma unroll
        for (int ks = 0; ks < BK; ks += 16) {
            uint32_t fah[4][4], fal[4][4];
#pragma unroll
            for (int mt = 0; mt < 4; mt++) {
                int row = wm * 64 + mt * 16 + (lane & 15);
                int col = ks + ((lane >> 4) << 3);
                ldm4(fah[mt], smem_u32(ah + row * ASTR + col));
                ldm4(fal[mt], smem_u32(al + row * ASTR + col));
            }
            uint32_t fbh[8], fbl[8];
#pragma unroll
            for (int p = 0; p < 2; p++) {
                if (NT) {
                    int row = wn * 32 + p * 16 + (lane & 7) + ((lane >> 4) << 3);
                    int col = ks + (lane & 8);
                    ldm4(&fbh[4 * p], smem_u32(bh + row * BSTR + col));
                    ldm4(&fbl[4 * p], smem_u32(bl + row * BSTR + col));
                } else {
                    int row = ks + (lane & 15);
                    int col = wn * 32 + p * 16 + ((lane >> 4) << 3);
                    ldm4t(&fbh[4 * p], smem_u32(bh + row * BSTR + col));
                    ldm4t(&fbl[4 * p], smem_u32(bl + row * BSTR + col));
                }
            }
#pragma unroll
            for (int mt = 0; mt < 4; mt++)
#pragma unroll
                for (int nt = 0; nt < 4; nt++) {
                    mma_bf16(c[mt][nt], fah[mt], fbh[2*nt], fbh[2*nt+1]);
                    mma_bf16(c[mt][nt], fah[mt], fbl[2*nt], fbl[2*nt+1]);
                    mma_bf16(c[mt][nt], fal[mt], fbh[2*nt], fbh[2*nt+1]);
                }
        }
        __syncthreads();
    }

    // ---- epilogue ----
#pragma unroll
    for (int mt = 0; mt < 4; mt++)
#pragma unroll
        for (int nt = 0; nt < 4; nt++) {
            int row = m0 + wm * 64 + mt * 16 + (lane >> 2);
            int col = n0 + wn * 32 + nt * 8 + (lane & 3) * 2;
            size_t o0 = coff + (size_t)row * ldc + col;
            size_t o1 = coff + (size_t)(row + 8) * ldc + col;
            float f0 = c[mt][nt][0], f1 = c[mt][nt][1];
            float f2 = c[mt][nt][2], f3 = c[mt][nt][3];
            if (C) {
                *(float2*)(C + o0) = make_float2(f0, f1);
                *(float2*)(C + o1) = make_float2(f2, f3);
            }
            if (Ch) {
                bf16 h0 = __float2bfloat16(f0), h1 = __float2bfloat16(f1);
                bf16 h2 = __float2bfloat16(f2), h3 = __float2bfloat16(f3);
                *(uint32_t*)(Ch + o0) = pack2bf(f0, f1) ;
                *(uint32_t*)(Ch + o1) = pack2bf(f2, f3);
                *(uint32_t*)(Cl + o0) = pack2bf(f0 - __bfloat162float(h0),
                                                f1 - __bfloat162float(h1));
                *(uint32_t*)(Cl + o1) = pack2bf(f2 - __bfloat162float(h2),
                                                f3 - __bfloat162float(h3));
            }
        }
}

// ---------------------------------------------------------------------------
// fp32 -> (hi, lo) bf16 planes
// ---------------------------------------------------------------------------
__global__ void split_fp32(const float* __restrict__ x,
                           bf16* __restrict__ h, bf16* __restrict__ l, int n)
{
    int i = blockIdx.x * 256 + threadIdx.x;
    if (i >= n) return;
    float v = x[i];
    bf16 hb = __float2bfloat16(v);
    h[i] = hb;
    l[i] = __float2bfloat16(v - __bfloat162float(hb));
}

// ---------------------------------------------------------------------------
// RoPE + q scale; qraw [B,S,H,D] -> q planes [B,H,S,D]; kraw [B,S,D] -> k planes
// ---------------------------------------------------------------------------
__global__ void rope_split(const int* __restrict__ pos,
                           bf16* __restrict__ qh, bf16* __restrict__ ql,
                           bf16* __restrict__ kh, bf16* __restrict__ kl)
{
    int t = blockIdx.x * 256 + threadIdx.x;
    const int TOT = BDIM * SEQ * (NH + 1) * HALF;
    if (t >= TOT) return;
    int i = t & (HALF - 1);
    int rest = t >> 7;
    int hh = rest % (NH + 1); rest /= (NH + 1);
    int s = rest % SEQ;
    int b = rest / SEQ;

    float p = (float)pos[b * SEQ + s];
    float freq = powf(10000.f, -(float)(2 * i) / (float)HD);
    float ang = p * freq;
    float sn, cs;
    sincosf(ang, &sn, &cs);

    if (hh < NH) {
        size_t base = ((size_t)(b * SEQ + s) * NH + hh) * HD;
        float x0 = g_qraw[base + i] * 0.0625f;
        float x1 = g_qraw[base + i + HALF] * 0.0625f;
        float y0 = x0 * cs - x1 * sn;
        float y1 = x1 * cs + x0 * sn;
        size_t ob = ((size_t)(b * NH + hh) * SEQ + s) * HD;
        bf16 h0 = __float2bfloat16(y0);
        qh[ob + i] = h0; ql[ob + i] = __float2bfloat16(y0 - __bfloat162float(h0));
        bf16 h1 = __float2bfloat16(y1);
        qh[ob + i + HALF] = h1; ql[ob + i + HALF] = __float2bfloat16(y1 - __bfloat162float(h1));
    } else {
        size_t base = (size_t)(b * SEQ + s) * HD;
        float x0 = g_kraw[base + i];
        float x1 = g_kraw[base + i + HALF];
        float y0 = x0 * cs - x1 * sn;
        float y1 = x1 * cs + x0 * sn;
        bf16 h0 = __float2bfloat16(y0);
        kh[base + i] = h0; kl[base + i] = __float2bfloat16(y0 - __bfloat162float(h0));
        bf16 h1 = __float2bfloat16(y1);
        kh[base + i + HALF] = h1; kl[base + i + HALF] = __float2bfloat16(y1 - __bfloat162float(h1));
    }
}

// ---------------------------------------------------------------------------
// Causal softmax in place + bf16 hi/lo planes for the PV GEMM.
// ---------------------------------------------------------------------------
__global__ __launch_bounds__(256) void softmax_causal_split(
    float* __restrict__ attn, bf16* __restrict__ ah, bf16* __restrict__ al)
{
    __shared__ float sm[SEQ];
    __shared__ float red[256];
    size_t row = blockIdx.x;
    int q = (int)(row % SEQ);
    float* r  = attn + row * SEQ;
    bf16*  rh = ah   + row * SEQ;
    bf16*  rl = al   + row * SEQ;
    int n = q + 1;
    int tid = threadIdx.x;

    float mx = -3.4e38f;
    for (int j = tid; j < n; j += 256) { float v = r[j]; sm[j] = v; mx = fmaxf(mx, v); }
    red[tid] = mx; __syncthreads();
    for (int s = 128; s > 0; s >>= 1) { if (tid < s) red[tid] = fmaxf(red[tid], red[tid + s]); __syncthreads(); }
    mx = red[0];
    __syncthreads();

    float sum = 0.f;
    for (int j = tid; j < n; j += 256) { float e = expf(sm[j] - mx); sm[j] = e; sum += e; }
    red[tid] = sum; __syncthreads();
    for (int s = 128; s > 0; s >>= 1) { if (tid < s) red[tid] += red[tid + s]; __syncthreads(); }
    float inv = 1.f / red[0];

    for (int j = tid; j < SEQ; j += 256) {
        float o = (j < n) ? sm[j] * inv : 0.f;
        r[j] = o;
        bf16 hb = __float2bfloat16(o);
        rh[j] = hb;
        rl[j] = __float2bfloat16(o - __bfloat162float(hb));
    }
}

// ---------------------------------------------------------------------------
// Host launcher
// ---------------------------------------------------------------------------
extern "C" void kernel_launch(void* const* d_in, const int* in_sizes, int n_in,
                              void* d_out, int out_size)
{
    const float* hidden = (const float*)d_in[0];
    const float* Wq     = (const float*)d_in[1];
    const float* Wk     = (const float*)d_in[2];
    const float* Wv     = (const float*)d_in[3];
    const float* Wo     = (const float*)d_in[4];
    const int*   pos    = (const int*)d_in[6];

    float *qraw, *kraw, *attn_s;
    bf16 *hid_h, *hid_l, *wq_h, *wq_l, *wk_h, *wk_l, *wv_h, *wv_l, *wo_h, *wo_l;
    bf16 *q_h, *q_l, *k_h, *k_l, *v_h, *v_l, *ah_h, *ah_l, *at_h, *at_l;

    cudaGetSymbolAddress((void**)&qraw, g_qraw);
    cudaGetSymbolAddress((void**)&kraw, g_kraw);
    cudaGetSymbolAddress((void**)&attn_s, g_attn_s);
    cudaGetSymbolAddress((void**)&hid_h, g_hid_h); cudaGetSymbolAddress((void**)&hid_l, g_hid_l);
    cudaGetSymbolAddress((void**)&wq_h, g_wq_h);   cudaGetSymbolAddress((void**)&wq_l, g_wq_l);
    cudaGetSymbolAddress((void**)&wk_h, g_wk_h);   cudaGetSymbolAddress((void**)&wk_l, g_wk_l);
    cudaGetSymbolAddress((void**)&wv_h, g_wv_h);   cudaGetSymbolAddress((void**)&wv_l, g_wv_l);
    cudaGetSymbolAddress((void**)&wo_h, g_wo_h);   cudaGetSymbolAddress((void**)&wo_l, g_wo_l);
    cudaGetSymbolAddress((void**)&q_h, g_q_h);     cudaGetSymbolAddress((void**)&q_l, g_q_l);
    cudaGetSymbolAddress((void**)&k_h, g_k_h);     cudaGetSymbolAddress((void**)&k_l, g_k_l);
    cudaGetSymbolAddress((void**)&v_h, g_v_h);     cudaGetSymbolAddress((void**)&v_l, g_v_l);
    cudaGetSymbolAddress((void**)&ah_h, g_ah_h);   cudaGetSymbolAddress((void**)&ah_l, g_ah_l);
    cudaGetSymbolAddress((void**)&at_h, g_at_h);   cudaGetSymbolAddress((void**)&at_l, g_at_l);

    float* out = (float*)d_out;
    const long long OUTE  = (long long)BDIM * SEQ * HID;
    const long long ATTNE = (long long)BDIM * NH * SEQ * SEQ;
    float* attn = ((long long)out_size >= OUTE + ATTNE) ? (out + OUTE) : attn_s;

    const int M = BDIM * SEQ;  // 4096

    // dynamic smem sizes
    const int A_BYTES  = STAGES * BM * (BK + 8) * 2 * 2;                 // Ah+Al
    const int B_NN     = STAGES * BK * (BN + 8) * 2 * 2;
    const int B_NT     = STAGES * BN * (BK + 8) * 2 * 2;
    const int SMEM_NN  = A_BYTES + B_NN;   // 113,664 B
    const int SMEM_NT  = A_BYTES + B_NT;   // 122,880 B
    cudaFuncSetAttribute(gemm_split<false>, cudaFuncAttributeMaxDynamicSharedMemorySize, SMEM_NN);
    cudaFuncSetAttribute(gemm_split<true>,  cudaFuncAttributeMaxDynamicSharedMemorySize, SMEM_NT);

    // splits of inputs
    { int n = BDIM*SEQ*HID;  split_fp32<<<n/256, 256>>>(hidden, hid_h, hid_l, n); }
    { int n = HID*NH*HD;     split_fp32<<<n/256, 256>>>(Wq, wq_h, wq_l, n); }
    { int n = HID*HD;        split_fp32<<<n/256, 256>>>(Wk, wk_h, wk_l, n); }
    { int n = HID*HD;        split_fp32<<<n/256, 256>>>(Wv, wv_h, wv_l, n); }
    { int n = NH*HD*HID;     split_fp32<<<n/256, 256>>>(Wo, wo_h, wo_l, n); }

    // projections: Q,K -> f32 (rope consumes); V -> bf16 planes directly
    gemm_split<false><<<dim3(HID/BN, M/BM, 1), 256, SMEM_NN>>>(
        hid_h, hid_l, wq_h, wq_l, qraw, nullptr, nullptr,
        HID, HID, HID, HID, 1, 0,0,0,0,0,0, 0);
    gemm_split<false><<<dim3(HD/BN, M/BM, 1), 256, SMEM_NN>>>(
        hid_h, hid_l, wk_h, wk_l, kraw, nullptr, nullptr,
        HID, HID, HD, HD, 1, 0,0,0,0,0,0, 0);
    gemm_split<false><<<dim3(HD/BN, M/BM, 1), 256, SMEM_NN>>>(
        hid_h, hid_l, wv_h, wv_l, nullptr, v_h, v_l,
        HID, HID, HD, HD, 1, 0,0,0,0,0,0, 0);

    // RoPE + split q/k
    { int TOT = BDIM*SEQ*(NH+1)*HALF; rope_split<<<(TOT+255)/256, 256>>>(pos, q_h, q_l, k_h, k_l); }

    // scores = q @ k^T (NT), causal tile skip
    gemm_split<true><<<dim3(SEQ/BN, SEQ/BM, BDIM*NH), 256, SMEM_NT>>>(
        q_h, q_l, k_h, k_l, attn, nullptr, nullptr,
        HD, HD, HD, SEQ,
        NH,
        (long long)NH*SEQ*HD, (long long)SEQ*HD,
        (long long)SEQ*HD, 0,
        (long long)NH*SEQ*SEQ, (long long)SEQ*SEQ,
        1);

    // softmax + attn planes
    softmax_causal_split<<<BDIM*NH*SEQ, 256>>>(attn, at_h, at_l);

    // PV: planes out directly (no f32 intermediate), causal K-limit
    gemm_split<false><<<dim3(HD/BN, SEQ/BM, BDIM*NH), 256, SMEM_NN>>>(
        at_h, at_l, v_h, v_l, nullptr, ah_h, ah_l,
        SEQ, SEQ, HD, NH*HD,
        NH,
        (long long)NH*SEQ*SEQ, (long long)SEQ*SEQ,
        (long long)SEQ*HD, 0,
        (long long)SEQ*NH*HD, (long long)HD,
        2);

    // out = ah @ Wo
    gemm_split<false><<<dim3(HID/BN, M/BM, 1), 256, SMEM_NN>>>(
        ah_h, ah_l, wo_h, wo_l, out, nullptr, nullptr,
        NH*HD, NH*HD, HID, HID, 1, 0,0,0,0,0,0, 0);
}

// round 9
// speedup vs baseline: 3.6522x; 1.5084x over previous
#include <cuda_runtime.h>
#include <cuda_fp16.h>
#include <math.h>
#include <stdint.h>

#define BDIM 2
#define SEQ  2048
#define HID  2048
#define NH   8
#define HD   256
#define HALF 128

#define BM 128
#define BN 128
#define BK 32
#define STAGES 3

typedef __half fp16;

// ------------------------- static device scratch ---------------------------
__device__ __align__(16) float g_qraw[BDIM*SEQ*NH*HD];
__device__ __align__(16) float g_kraw[BDIM*SEQ*HD];
__device__ __align__(16) float g_attn_s[(size_t)BDIM*NH*SEQ*SEQ];

__device__ __align__(16) fp16 g_hid_h[BDIM*SEQ*HID], g_hid_l[BDIM*SEQ*HID];
__device__ __align__(16) fp16 g_wq[HID*NH*HD];            // [2048,2048] single
__device__ __align__(16) fp16 g_wkv[HID*2*HD];            // [2048,512]  Wk|Wv
__device__ __align__(16) fp16 g_wo[NH*HD*HID];            // [2048,2048]
__device__ __align__(16) fp16 g_q_h[BDIM*NH*SEQ*HD], g_q_l[BDIM*NH*SEQ*HD];
__device__ __align__(16) fp16 g_k[BDIM*SEQ*HD];           // single
__device__ __align__(16) fp16 g_v[BDIM*SEQ*HD];           // single
__device__ __align__(16) fp16 g_at_h[(size_t)BDIM*NH*SEQ*SEQ];
__device__ __align__(16) fp16 g_at_l[(size_t)BDIM*NH*SEQ*SEQ];
__device__ __align__(16) fp16 g_ah_h[BDIM*SEQ*NH*HD], g_ah_l[BDIM*SEQ*NH*HD];

// ------------------------------- helpers -----------------------------------
__device__ __forceinline__ uint32_t smem_u32(const void* p) {
    return (uint32_t)__cvta_generic_to_shared(p);
}
__device__ __forceinline__ void cp16a(void* dst, const void* src) {
    asm volatile("cp.async.cg.shared.global [%0], [%1], 16;\n"
                 :: "r"(smem_u32(dst)), "l"(src));
}
__device__ __forceinline__ void cp_commit() { asm volatile("cp.async.commit_group;\n"); }
template<int N> __device__ __forceinline__ void cp_wait() {
    asm volatile("cp.async.wait_group %0;\n" :: "n"(N));
}
__device__ __forceinline__ void ldm4(uint32_t r[4], uint32_t a) {
    asm volatile("ldmatrix.sync.aligned.m8n8.x4.shared.b16 {%0,%1,%2,%3}, [%4];\n"
                 : "=r"(r[0]), "=r"(r[1]), "=r"(r[2]), "=r"(r[3]) : "r"(a));
}
__device__ __forceinline__ void ldm4t(uint32_t r[4], uint32_t a) {
    asm volatile("ldmatrix.sync.aligned.m8n8.x4.trans.shared.b16 {%0,%1,%2,%3}, [%4];\n"
                 : "=r"(r[0]), "=r"(r[1]), "=r"(r[2]), "=r"(r[3]) : "r"(a));
}
__device__ __forceinline__ void mma_fp16(float c[4], const uint32_t a[4],
                                         uint32_t b0, uint32_t b1) {
    asm volatile(
        "mma.sync.aligned.m16n8k16.row.col.f32.f16.f16.f32 "
        "{%0,%1,%2,%3}, {%4,%5,%6,%7}, {%8,%9}, {%0,%1,%2,%3};\n"
        : "+f"(c[0]), "+f"(c[1]), "+f"(c[2]), "+f"(c[3])
        : "r"(a[0]), "r"(a[1]), "r"(a[2]), "r"(a[3]), "r"(b0), "r"(b1));
}
__device__ __forceinline__ uint32_t pack2h(float a, float b) {
    __half2 v = __floats2half2_rn(a, b);
    return *(uint32_t*)&v;
}

// ---------------------------------------------------------------------------
// 2-pass fp16 asymmetric GEMM: C = (Ah+Al)[M,K] @ B, B single fp16.
// NT=false: B [K,N] row-major.  NT=true: B [N,K] row-major (C = A·B^T).
// epi: 0 = f32 C;  1 = fp16 hi/lo planes Ch/Cl;  2 = KV split (cols<256 ->
//      f32 C (kraw), cols>=256 -> fp16 single Ch (v)), both ldc=256.
// cmode: 0 none; 1 (NT) causal tile-skip; 2 causal K-limit.
// 256 threads, warps 2(m) x 4(n), warp tile 64x32. 3-stage cp.async.
// ---------------------------------------------------------------------------
template<bool NT>
__global__ __launch_bounds__(256, 2) void gemm2p(
    const fp16* __restrict__ Ah, const fp16* __restrict__ Al,
    const fp16* __restrict__ Bs,
    float* __restrict__ C, fp16* __restrict__ Ch, fp16* __restrict__ Cl,
    int K, int lda, int ldb, int ldc,
    int zdiv, long long Ao, long long Ai, long long Bo, long long Bi,
    long long Co, long long Ci, int cmode, int epi)
{
    if (NT && cmode == 1 && blockIdx.x > blockIdx.y) return;

    constexpr int ASTR  = BK + 8;                  // 40
    constexpr int BROWS = NT ? BN : BK;
    constexpr int BSTR  = NT ? (BK + 8) : (BN + 8);
    constexpr int AELEM = BM * ASTR;               // 5120
    constexpr int BELEM = BROWS * BSTR;

    extern __shared__ fp16 smem[];
    fp16* pAh = smem;
    fp16* pAl = pAh + STAGES * AELEM;
    fp16* pB  = pAl + STAGES * AELEM;

    int z = blockIdx.z;
    int zo = z / zdiv, zi = z - zo * zdiv;
    Ah += zo * Ao + zi * Ai;  Al += zo * Ao + zi * Ai;
    Bs += zo * Bo + zi * Bi;
    long long coff = zo * Co + zi * Ci;

    int m0 = blockIdx.y * BM, n0 = blockIdx.x * BN;
    int tid = threadIdx.x, lane = tid & 31, wid = tid >> 5;
    int wm = wid & 1, wn = wid >> 1;

    int kmax = (cmode == 2) ? min(K, m0 + BM) : K;
    int niter = kmax / BK;

    const int ar0 = tid >> 2,         ac0 = (tid & 3) * 8;
    const int ar1 = (tid + 256) >> 2, ac1 = ac0;
    const int br0 = tid >> 4,         bc0 = (tid & 15) * 8;
    const int br1 = (tid + 256) >> 4, bc1 = bc0;

    float c[4][4][4];
#pragma unroll
    for (int mt = 0; mt < 4; mt++)
#pragma unroll
        for (int nt = 0; nt < 4; nt++)
#pragma unroll
            for (int i = 0; i < 4; i++) c[mt][nt][i] = 0.f;

    auto load_stage = [&](int st, int k0) {
        fp16* ah = pAh + st * AELEM;  fp16* al = pAl + st * AELEM;
        fp16* bb = pB  + st * BELEM;
        cp16a(ah + ar0 * ASTR + ac0, Ah + (size_t)(m0 + ar0) * lda + k0 + ac0);
        cp16a(ah + ar1 * ASTR + ac1, Ah + (size_t)(m0 + ar1) * lda + k0 + ac1);
        cp16a(al + ar0 * ASTR + ac0, Al + (size_t)(m0 + ar0) * lda + k0 + ac0);
        cp16a(al + ar1 * ASTR + ac1, Al + (size_t)(m0 + ar1) * lda + k0 + ac1);
        if (NT) {
            cp16a(bb + ar0 * BSTR + ac0, Bs + (size_t)(n0 + ar0) * ldb + k0 + ac0);
            cp16a(bb + ar1 * BSTR + ac1, Bs + (size_t)(n0 + ar1) * ldb + k0 + ac1);
        } else {
            cp16a(bb + br0 * BSTR + bc0, Bs + (size_t)(k0 + br0) * ldb + n0 + bc0);
            cp16a(bb + br1 * BSTR + bc1, Bs + (size_t)(k0 + br1) * ldb + n0 + bc1);
        }
    };

#pragma unroll
    for (int s = 0; s < STAGES - 1; s++) {
        if (s < niter) load_stage(s, s * BK);
        cp_commit();
    }

    for (int it = 0; it < niter; it++) {
        cp_wait<STAGES - 2>();
        __syncthreads();

        int nk = it + STAGES - 1;
        if (nk < niter) load_stage(nk % STAGES, nk * BK);
        cp_commit();

        int st = it % STAGES;
        const fp16* ah = pAh + st * AELEM;
        const fp16* al = pAl + st * AELEM;
        const fp16* bb = pB  + st * BELEM;

#pragma unroll
        for (int ks = 0; ks < BK; ks += 16) {
            uint32_t fa[4][4], fb[8];
#pragma unroll
            for (int mt = 0; mt < 4; mt++) {
                int row = wm * 64 + mt * 16 + (lane & 15);
                int col = ks + ((lane >> 4) << 3);
                ldm4(fa[mt], smem_u32(ah + row * ASTR + col));
            }
#pragma unroll
            for (int p = 0; p < 2; p++) {
                if (NT) {
                    int row = wn * 32 + p * 16 + (lane & 7) + ((lane >> 4) << 3);
                    int col = ks + (lane & 8);
                    ldm4(&fb[4 * p], smem_u32(bb + row * BSTR + col));
                } else {
                    int row = ks + (lane & 15);
                    int col = wn * 32 + p * 16 + ((lane >> 4) << 3);
                    ldm4t(&fb[4 * p], smem_u32(bb + row * BSTR + col));
                }
            }
            // pass 0: Ah * B
#pragma unroll
            for (int mt = 0; mt < 4; mt++)
#pragma unroll
                for (int nt = 0; nt < 4; nt++)
                    mma_fp16(c[mt][nt], fa[mt], fb[2*nt], fb[2*nt+1]);
            // reload lo fragments into the same regs, pass 1: Al * B
#pragma unroll
            for (int mt = 0; mt < 4; mt++) {
                int row = wm * 64 + mt * 16 + (lane & 15);
                int col = ks + ((lane >> 4) << 3);
                ldm4(fa[mt], smem_u32(al + row * ASTR + col));
            }
#pragma unroll
            for (int mt = 0; mt < 4; mt++)
#pragma unroll
                for (int nt = 0; nt < 4; nt++)
                    mma_fp16(c[mt][nt], fa[mt], fb[2*nt], fb[2*nt+1]);
        }
        __syncthreads();
    }

    // ---- epilogue ----
    int mode = epi;
    int nbase = n0;
    if (epi == 2) {
        if (n0 < 256) { mode = 0; }
        else          { mode = 3; nbase = n0 - 256; }
    }
#pragma unroll
    for (int mt = 0; mt < 4; mt++)
#pragma unroll
        for (int nt = 0; nt < 4; nt++) {
            int row = m0 + wm * 64 + mt * 16 + (lane >> 2);
            int col = nbase + wn * 32 + nt * 8 + (lane & 3) * 2;
            size_t o0 = (size_t)coff + (size_t)row * ldc + col;
            size_t o1 = (size_t)coff + (size_t)(row + 8) * ldc + col;
            float f0 = c[mt][nt][0], f1 = c[mt][nt][1];
            float f2 = c[mt][nt][2], f3 = c[mt][nt][3];
            if (mode == 0) {
                *(float2*)(C + o0) = make_float2(f0, f1);
                *(float2*)(C + o1) = make_float2(f2, f3);
            } else if (mode == 1) {
                fp16 h0 = __float2half_rn(f0), h1 = __float2half_rn(f1);
                fp16 h2 = __float2half_rn(f2), h3 = __float2half_rn(f3);
                *(uint32_t*)(Ch + o0) = pack2h(f0, f1);
                *(uint32_t*)(Ch + o1) = pack2h(f2, f3);
                *(uint32_t*)(Cl + o0) = pack2h(f0 - __half2float(h0), f1 - __half2float(h1));
                *(uint32_t*)(Cl + o1) = pack2h(f2 - __half2float(h2), f3 - __half2float(h3));
            } else {  // mode 3: fp16 single
                *(uint32_t*)(Ch + o0) = pack2h(f0, f1);
                *(uint32_t*)(Ch + o1) = pack2h(f2, f3);
            }
        }
}

// ---------------------------------------------------------------------------
// fp32 -> fp16 hi/lo planes
// ---------------------------------------------------------------------------
__global__ void split_h(const float* __restrict__ x,
                        fp16* __restrict__ h, fp16* __restrict__ l, int n)
{
    int i = blockIdx.x * 256 + threadIdx.x;
    if (i >= n) return;
    float v = x[i];
    fp16 hb = __float2half_rn(v);
    h[i] = hb;
    l[i] = __float2half_rn(v - __half2float(hb));
}

// f32 [R,C] -> fp16 single, dst row stride dstride, col offset coff
__global__ void convW(const float* __restrict__ x, fp16* __restrict__ d,
                      int C, int dstride, int coff, int n)
{
    int i = blockIdx.x * 256 + threadIdx.x;
    if (i >= n) return;
    int r = i / C, c = i - r * C;
    d[(size_t)r * dstride + coff + c] = __float2half_rn(x[i]);
}

// ---------------------------------------------------------------------------
// RoPE: qraw [B,S,H,D] -> q hi/lo fp16 [B,H,S,D] (scaled 1/16);
//       kraw [B,S,D]   -> k single fp16 [B,S,D]
// ---------------------------------------------------------------------------
__global__ void rope_split(const int* __restrict__ pos,
                           fp16* __restrict__ qh, fp16* __restrict__ ql,
                           fp16* __restrict__ k)
{
    int t = blockIdx.x * 256 + threadIdx.x;
    const int TOT = BDIM * SEQ * (NH + 1) * HALF;
    if (t >= TOT) return;
    int i = t & (HALF - 1);
    int rest = t >> 7;
    int hh = rest % (NH + 1); rest /= (NH + 1);
    int s = rest % SEQ;
    int b = rest / SEQ;

    float p = (float)pos[b * SEQ + s];
    float freq = powf(10000.f, -(float)(2 * i) / (float)HD);
    float ang = p * freq;
    float sn, cs;
    sincosf(ang, &sn, &cs);

    if (hh < NH) {
        size_t base = ((size_t)(b * SEQ + s) * NH + hh) * HD;
        float x0 = g_qraw[base + i] * 0.0625f;
        float x1 = g_qraw[base + i + HALF] * 0.0625f;
        float y0 = x0 * cs - x1 * sn;
        float y1 = x1 * cs + x0 * sn;
        size_t ob = ((size_t)(b * NH + hh) * SEQ + s) * HD;
        fp16 h0 = __float2half_rn(y0);
        qh[ob + i] = h0; ql[ob + i] = __float2half_rn(y0 - __half2float(h0));
        fp16 h1 = __float2half_rn(y1);
        qh[ob + i + HALF] = h1; ql[ob + i + HALF] = __float2half_rn(y1 - __half2float(h1));
    } else {
        size_t base = (size_t)(b * SEQ + s) * HD;
        float x0 = g_kraw[base + i];
        float x1 = g_kraw[base + i + HALF];
        k[base + i]        = __float2half_rn(x0 * cs - x1 * sn);
        k[base + i + HALF] = __float2half_rn(x1 * cs + x0 * sn);
    }
}

// ---------------------------------------------------------------------------
// Causal softmax in place + fp16 hi/lo planes for PV.
// ---------------------------------------------------------------------------
__global__ __launch_bounds__(256) void softmax_causal_split(
    float* __restrict__ attn, fp16* __restrict__ ah, fp16* __restrict__ al)
{
    __shared__ float sm[SEQ];
    __shared__ float red[256];
    size_t row = blockIdx.x;
    int q = (int)(row % SEQ);
    float* r  = attn + row * SEQ;
    fp16*  rh = ah   + row * SEQ;
    fp16*  rl = al   + row * SEQ;
    int n = q + 1;
    int tid = threadIdx.x;

    float mx = -3.4e38f;
    for (int j = tid; j < n; j += 256) { float v = r[j]; sm[j] = v; mx = fmaxf(mx, v); }
    red[tid] = mx; __syncthreads();
    for (int s = 128; s > 0; s >>= 1) { if (tid < s) red[tid] = fmaxf(red[tid], red[tid + s]); __syncthreads(); }
    mx = red[0];
    __syncthreads();

    float sum = 0.f;
    for (int j = tid; j < n; j += 256) { float e = expf(sm[j] - mx); sm[j] = e; sum += e; }
    red[tid] = sum; __syncthreads();
    for (int s = 128; s > 0; s >>= 1) { if (tid < s) red[tid] += red[tid + s]; __syncthreads(); }
    float inv = 1.f / red[0];

    for (int j = tid; j < SEQ; j += 256) {
        float o = (j < n) ? sm[j] * inv : 0.f;
        r[j] = o;
        fp16 hb = __float2half_rn(o);
        rh[j] = hb;
        rl[j] = __float2half_rn(o - __half2float(hb));
    }
}

// ---------------------------------------------------------------------------
// Host launcher
// ---------------------------------------------------------------------------
extern "C" void kernel_launch(void* const* d_in, const int* in_sizes, int n_in,
                              void* d_out, int out_size)
{
    const float* hidden = (const float*)d_in[0];
    const float* Wq     = (const float*)d_in[1];
    const float* Wk     = (const float*)d_in[2];
    const float* Wv     = (const float*)d_in[3];
    const float* Wo     = (const float*)d_in[4];
    const int*   pos    = (const int*)d_in[6];

    float *qraw, *kraw, *attn_s;
    fp16 *hid_h, *hid_l, *wq, *wkv, *wo;
    fp16 *q_h, *q_l, *k, *v, *at_h, *at_l, *ah_h, *ah_l;

    cudaGetSymbolAddress((void**)&qraw, g_qraw);
    cudaGetSymbolAddress((void**)&kraw, g_kraw);
    cudaGetSymbolAddress((void**)&attn_s, g_attn_s);
    cudaGetSymbolAddress((void**)&hid_h, g_hid_h); cudaGetSymbolAddress((void**)&hid_l, g_hid_l);
    cudaGetSymbolAddress((void**)&wq,  g_wq);
    cudaGetSymbolAddress((void**)&wkv, g_wkv);
    cudaGetSymbolAddress((void**)&wo,  g_wo);
    cudaGetSymbolAddress((void**)&q_h, g_q_h);  cudaGetSymbolAddress((void**)&q_l, g_q_l);
    cudaGetSymbolAddress((void**)&k,   g_k);
    cudaGetSymbolAddress((void**)&v,   g_v);
    cudaGetSymbolAddress((void**)&at_h, g_at_h); cudaGetSymbolAddress((void**)&at_l, g_at_l);
    cudaGetSymbolAddress((void**)&ah_h, g_ah_h); cudaGetSymbolAddress((void**)&ah_l, g_ah_l);

    float* out = (float*)d_out;
    const long long OUTE  = (long long)BDIM * SEQ * HID;
    const long long ATTNE = (long long)BDIM * NH * SEQ * SEQ;
    float* attn = ((long long)out_size >= OUTE + ATTNE) ? (out + OUTE) : attn_s;

    const int M = BDIM * SEQ;  // 4096

    // dynamic smem: A hi/lo (2 planes) + B (1 plane)
    const int SMEM_NN = STAGES * (2 * BM * (BK + 8) + BK * (BN + 8)) * 2;  // 87,552
    const int SMEM_NT = STAGES * (3 * BM * (BK + 8)) * 2;                  // 92,160
    cudaFuncSetAttribute(gemm2p<false>, cudaFuncAttributeMaxDynamicSharedMemorySize, SMEM_NN);
    cudaFuncSetAttribute(gemm2p<true>,  cudaFuncAttributeMaxDynamicSharedMemorySize, SMEM_NT);

    // input conversions
    { int n = BDIM*SEQ*HID; split_h<<<n/256, 256>>>(hidden, hid_h, hid_l, n); }
    { int n = HID*NH*HD; convW<<<(n+255)/256, 256>>>(Wq, wq,  NH*HD, NH*HD, 0,   n); }
    { int n = HID*HD;    convW<<<(n+255)/256, 256>>>(Wk, wkv, HD,    2*HD,  0,   n); }
    { int n = HID*HD;    convW<<<(n+255)/256, 256>>>(Wv, wkv, HD,    2*HD,  HD,  n); }
    { int n = NH*HD*HID; convW<<<(n+255)/256, 256>>>(Wo, wo,  HID,   HID,   0,   n); }

    // Q projection -> qraw f32
    gemm2p<false><<<dim3(HID/BN, M/BM, 1), 256, SMEM_NN>>>(
        hid_h, hid_l, wq, qraw, nullptr, nullptr,
        HID, HID, NH*HD, HID, 1, 0,0,0,0,0,0, 0, 0);

    // K|V projection (merged, N=512): cols<256 -> kraw f32; cols>=256 -> v fp16
    gemm2p<false><<<dim3(2*HD/BN, M/BM, 1), 256, SMEM_NN>>>(
        hid_h, hid_l, wkv, kraw, v, nullptr,
        HID, HID, 2*HD, HD, 1, 0,0,0,0,0,0, 0, 2);

    // RoPE + splits
    { int TOT = BDIM*SEQ*(NH+1)*HALF; rope_split<<<(TOT+255)/256, 256>>>(pos, q_h, q_l, k); }

    // scores = q @ k^T (NT), causal tile skip -> attn f32
    gemm2p<true><<<dim3(SEQ/BN, SEQ/BM, BDIM*NH), 256, SMEM_NT>>>(
        q_h, q_l, k, attn, nullptr, nullptr,
        HD, HD, HD, SEQ,
        NH,
        (long long)NH*SEQ*HD, (long long)SEQ*HD,
        (long long)SEQ*HD, 0,
        (long long)NH*SEQ*SEQ, (long long)SEQ*SEQ,
        1, 0);

    // softmax + attn planes
    softmax_causal_split<<<BDIM*NH*SEQ, 256>>>(attn, at_h, at_l);

    // PV: planes out, causal K-limit
    gemm2p<false><<<dim3(HD/BN, SEQ/BM, BDIM*NH), 256, SMEM_NN>>>(
        at_h, at_l, v, nullptr, ah_h, ah_l,
        SEQ, SEQ, HD, NH*HD,
        NH,
        (long long)NH*SEQ*SEQ, (long long)SEQ*SEQ,
        (long long)SEQ*HD, 0,
        (long long)SEQ*NH*HD, (long long)HD,
        2, 1);

    // out = ah @ Wo
    gemm2p<false><<<dim3(HID/BN, M/BM, 1), 256, SMEM_NN>>>(
        ah_h, ah_l, wo, out, nullptr, nullptr,
        NH*HD, NH*HD, HID, HID, 1, 0,0,0,0,0,0, 0, 0);
}

// round 10
// speedup vs baseline: 4.6649x; 1.2773x over previous
#include <cuda_runtime.h>
#include <cuda_fp16.h>
#include <math.h>
#include <stdint.h>

#define BDIM 2
#define SEQ  2048
#define HID  2048
#define NH   8
#define HD   256
#define HALF 128

#define BM 128
#define BN 128
#define BK 32
#define STAGES 3

typedef __half fp16;

// ------------------------- static device scratch ---------------------------
__device__ __align__(16) float g_qraw[BDIM*SEQ*NH*HD];
__device__ __align__(16) float g_kraw[BDIM*SEQ*HD];
__device__ __align__(16) float g_attn_s[(size_t)BDIM*NH*SEQ*SEQ];

__device__ __align__(16) fp16 g_hid[BDIM*SEQ*HID];        // single fp16
__device__ __align__(16) fp16 g_wq[HID*NH*HD];            // [2048,2048]
__device__ __align__(16) fp16 g_wkv[HID*2*HD];            // [2048,512] Wk|Wv
__device__ __align__(16) fp16 g_wo[NH*HD*HID];            // [2048,2048]
__device__ __align__(16) fp16 g_q_h[BDIM*NH*SEQ*HD], g_q_l[BDIM*NH*SEQ*HD];
__device__ __align__(16) fp16 g_k[BDIM*SEQ*HD];
__device__ __align__(16) fp16 g_v[BDIM*SEQ*HD];
__device__ __align__(16) fp16 g_at_h[(size_t)BDIM*NH*SEQ*SEQ];
__device__ __align__(16) fp16 g_at_l[(size_t)BDIM*NH*SEQ*SEQ];
__device__ __align__(16) fp16 g_ah[BDIM*SEQ*NH*HD];       // single fp16

// ------------------------------- helpers -----------------------------------
__device__ __forceinline__ uint32_t smem_u32(const void* p) {
    return (uint32_t)__cvta_generic_to_shared(p);
}
__device__ __forceinline__ void cp16a(void* dst, const void* src) {
    asm volatile("cp.async.cg.shared.global [%0], [%1], 16;\n"
                 :: "r"(smem_u32(dst)), "l"(src));
}
__device__ __forceinline__ void cp_commit() { asm volatile("cp.async.commit_group;\n"); }
template<int N> __device__ __forceinline__ void cp_wait() {
    asm volatile("cp.async.wait_group %0;\n" :: "n"(N));
}
__device__ __forceinline__ void ldm4(uint32_t r[4], uint32_t a) {
    asm volatile("ldmatrix.sync.aligned.m8n8.x4.shared.b16 {%0,%1,%2,%3}, [%4];\n"
                 : "=r"(r[0]), "=r"(r[1]), "=r"(r[2]), "=r"(r[3]) : "r"(a));
}
__device__ __forceinline__ void ldm4t(uint32_t r[4], uint32_t a) {
    asm volatile("ldmatrix.sync.aligned.m8n8.x4.trans.shared.b16 {%0,%1,%2,%3}, [%4];\n"
                 : "=r"(r[0]), "=r"(r[1]), "=r"(r[2]), "=r"(r[3]) : "r"(a));
}
__device__ __forceinline__ void mma_fp16(float c[4], const uint32_t a[4],
                                         uint32_t b0, uint32_t b1) {
    asm volatile(
        "mma.sync.aligned.m16n8k16.row.col.f32.f16.f16.f32 "
        "{%0,%1,%2,%3}, {%4,%5,%6,%7}, {%8,%9}, {%0,%1,%2,%3};\n"
        : "+f"(c[0]), "+f"(c[1]), "+f"(c[2]), "+f"(c[3])
        : "r"(a[0]), "r"(a[1]), "r"(a[2]), "r"(a[3]), "r"(b0), "r"(b1));
}
__device__ __forceinline__ uint32_t pack2h(float a, float b) {
    __half2 v = __floats2half2_rn(a, b);
    return *(uint32_t*)&v;
}

// ---------------------------------------------------------------------------
// fp16 GEMM, optional 2nd pass with A-lo plane (Al may be nullptr).
// C = (Ah [+Al])[M,K] @ B.
// NT=false: B [K,N] row-major.  NT=true: B [N,K] row-major (C = A·B^T).
// epi: 0 f32 C; 1 fp16 hi/lo planes; 2 KV split (cols<256 f32 C, >=256 fp16 Ch,
//      both ldc=256); 3 fp16 single Ch.
// cmode: 0 none; 1 (NT) causal tile-skip; 2 causal K-limit.
// 256 threads, warps 2(m) x 4(n), warp tile 64x32, 3-stage cp.async.
// ---------------------------------------------------------------------------
template<bool NT>
__global__ __launch_bounds__(256, 2) void gemm2p(
    const fp16* __restrict__ Ah, const fp16* __restrict__ Al,
    const fp16* __restrict__ Bs,
    float* __restrict__ C, fp16* __restrict__ Ch, fp16* __restrict__ Cl,
    int K, int lda, int ldb, int ldc,
    int zdiv, long long Ao, long long Ai, long long Bo, long long Bi,
    long long Co, long long Ci, int cmode, int epi)
{
    if (NT && cmode == 1 && blockIdx.x > blockIdx.y) return;

    constexpr int ASTR  = BK + 8;                  // 40
    constexpr int BROWS = NT ? BN : BK;
    constexpr int BSTR  = NT ? (BK + 8) : (BN + 8);
    constexpr int AELEM = BM * ASTR;               // 5120
    constexpr int BELEM = BROWS * BSTR;

    extern __shared__ fp16 smem[];
    fp16* pAh = smem;
    fp16* pAl = pAh + STAGES * AELEM;
    fp16* pB  = pAl + STAGES * AELEM;

    const bool has_lo = (Al != nullptr);

    int z = blockIdx.z;
    int zo = z / zdiv, zi = z - zo * zdiv;
    Ah += zo * Ao + zi * Ai;
    if (has_lo) Al += zo * Ao + zi * Ai;
    Bs += zo * Bo + zi * Bi;
    long long coff = zo * Co + zi * Ci;

    int m0 = blockIdx.y * BM, n0 = blockIdx.x * BN;
    int tid = threadIdx.x, lane = tid & 31, wid = tid >> 5;
    int wm = wid & 1, wn = wid >> 1;

    int kmax = (cmode == 2) ? min(K, m0 + BM) : K;
    int niter = kmax / BK;

    const int ar0 = tid >> 2,         ac0 = (tid & 3) * 8;
    const int ar1 = (tid + 256) >> 2, ac1 = ac0;
    const int br0 = tid >> 4,         bc0 = (tid & 15) * 8;
    const int br1 = (tid + 256) >> 4, bc1 = bc0;

    float c[4][4][4];
#pragma unroll
    for (int mt = 0; mt < 4; mt++)
#pragma unroll
        for (int nt = 0; nt < 4; nt++)
#pragma unroll
            for (int i = 0; i < 4; i++) c[mt][nt][i] = 0.f;

    auto load_stage = [&](int st, int k0) {
        fp16* ah = pAh + st * AELEM;  fp16* al = pAl + st * AELEM;
        fp16* bb = pB  + st * BELEM;
        cp16a(ah + ar0 * ASTR + ac0, Ah + (size_t)(m0 + ar0) * lda + k0 + ac0);
        cp16a(ah + ar1 * ASTR + ac1, Ah + (size_t)(m0 + ar1) * lda + k0 + ac1);
        if (has_lo) {
            cp16a(al + ar0 * ASTR + ac0, Al + (size_t)(m0 + ar0) * lda + k0 + ac0);
            cp16a(al + ar1 * ASTR + ac1, Al + (size_t)(m0 + ar1) * lda + k0 + ac1);
        }
        if (NT) {
            cp16a(bb + ar0 * BSTR + ac0, Bs + (size_t)(n0 + ar0) * ldb + k0 + ac0);
            cp16a(bb + ar1 * BSTR + ac1, Bs + (size_t)(n0 + ar1) * ldb + k0 + ac1);
        } else {
            cp16a(bb + br0 * BSTR + bc0, Bs + (size_t)(k0 + br0) * ldb + n0 + bc0);
            cp16a(bb + br1 * BSTR + bc1, Bs + (size_t)(k0 + br1) * ldb + n0 + bc1);
        }
    };

#pragma unroll
    for (int s = 0; s < STAGES - 1; s++) {
        if (s < niter) load_stage(s, s * BK);
        cp_commit();
    }

    for (int it = 0; it < niter; it++) {
        cp_wait<STAGES - 2>();
        __syncthreads();

        int nk = it + STAGES - 1;
        if (nk < niter) load_stage(nk % STAGES, nk * BK);
        cp_commit();

        int st = it % STAGES;
        const fp16* ah = pAh + st * AELEM;
        const fp16* al = pAl + st * AELEM;
        const fp16* bb = pB  + st * BELEM;

#pragma unroll
        for (int ks = 0; ks < BK; ks += 16) {
            uint32_t fa[4][4], fb[8];
#pragma unroll
            for (int mt = 0; mt < 4; mt++) {
                int row = wm * 64 + mt * 16 + (lane & 15);
                int col = ks + ((lane >> 4) << 3);
                ldm4(fa[mt], smem_u32(ah + row * ASTR + col));
            }
#pragma unroll
            for (int p = 0; p < 2; p++) {
                if (NT) {
                    int row = wn * 32 + p * 16 + (lane & 7) + ((lane >> 4) << 3);
                    int col = ks + (lane & 8);
                    ldm4(&fb[4 * p], smem_u32(bb + row * BSTR + col));
                } else {
                    int row = ks + (lane & 15);
                    int col = wn * 32 + p * 16 + ((lane >> 4) << 3);
                    ldm4t(&fb[4 * p], smem_u32(bb + row * BSTR + col));
                }
            }
#pragma unroll
            for (int mt = 0; mt < 4; mt++)
#pragma unroll
                for (int nt = 0; nt < 4; nt++)
                    mma_fp16(c[mt][nt], fa[mt], fb[2*nt], fb[2*nt+1]);
            if (has_lo) {
#pragma unroll
                for (int mt = 0; mt < 4; mt++) {
                    int row = wm * 64 + mt * 16 + (lane & 15);
                    int col = ks + ((lane >> 4) << 3);
                    ldm4(fa[mt], smem_u32(al + row * ASTR + col));
                }
#pragma unroll
                for (int mt = 0; mt < 4; mt++)
#pragma unroll
                    for (int nt = 0; nt < 4; nt++)
                        mma_fp16(c[mt][nt], fa[mt], fb[2*nt], fb[2*nt+1]);
            }
        }
        __syncthreads();
    }

    // ---- epilogue ----
    int mode = epi;
    int nbase = n0;
    if (epi == 2) {
        if (n0 < 256) { mode = 0; }
        else          { mode = 3; nbase = n0 - 256; }
    }
#pragma unroll
    for (int mt = 0; mt < 4; mt++)
#pragma unroll
        for (int nt = 0; nt < 4; nt++) {
            int row = m0 + wm * 64 + mt * 16 + (lane >> 2);
            int col = nbase + wn * 32 + nt * 8 + (lane & 3) * 2;
            size_t o0 = (size_t)coff + (size_t)row * ldc + col;
            size_t o1 = (size_t)coff + (size_t)(row + 8) * ldc + col;
            float f0 = c[mt][nt][0], f1 = c[mt][nt][1];
            float f2 = c[mt][nt][2], f3 = c[mt][nt][3];
            if (mode == 0) {
                *(float2*)(C + o0) = make_float2(f0, f1);
                *(float2*)(C + o1) = make_float2(f2, f3);
            } else if (mode == 1) {
                fp16 h0 = __float2half_rn(f0), h1 = __float2half_rn(f1);
                fp16 h2 = __float2half_rn(f2), h3 = __float2half_rn(f3);
                *(uint32_t*)(Ch + o0) = pack2h(f0, f1);
                *(uint32_t*)(Ch + o1) = pack2h(f2, f3);
                *(uint32_t*)(Cl + o0) = pack2h(f0 - __half2float(h0), f1 - __half2float(h1));
                *(uint32_t*)(Cl + o1) = pack2h(f2 - __half2float(h2), f3 - __half2float(h3));
            } else {  // mode 3: fp16 single
                *(uint32_t*)(Ch + o0) = pack2h(f0, f1);
                *(uint32_t*)(Ch + o1) = pack2h(f2, f3);
            }
        }
}

// ---------------------------------------------------------------------------
// f32 [R,C] -> fp16 single, dst row stride dstride, col offset coff
// ---------------------------------------------------------------------------
__global__ void convW(const float* __restrict__ x, fp16* __restrict__ d,
                      int C, int dstride, int coff, int n)
{
    int i = blockIdx.x * 256 + threadIdx.x;
    if (i >= n) return;
    int r = i / C, c = i - r * C;
    d[(size_t)r * dstride + coff + c] = __float2half_rn(x[i]);
}

// ---------------------------------------------------------------------------
// RoPE: qraw [B,S,H,D] -> q hi/lo fp16 [B,H,S,D] (scaled 1/16);
//       kraw [B,S,D]   -> k single fp16 [B,S,D]
// ---------------------------------------------------------------------------
__global__ void rope_split(const int* __restrict__ pos,
                           fp16* __restrict__ qh, fp16* __restrict__ ql,
                           fp16* __restrict__ k)
{
    int t = blockIdx.x * 256 + threadIdx.x;
    const int TOT = BDIM * SEQ * (NH + 1) * HALF;
    if (t >= TOT) return;
    int i = t & (HALF - 1);
    int rest = t >> 7;
    int hh = rest % (NH + 1); rest /= (NH + 1);
    int s = rest % SEQ;
    int b = rest / SEQ;

    float p = (float)pos[b * SEQ + s];
    float freq = powf(10000.f, -(float)(2 * i) / (float)HD);
    float ang = p * freq;
    float sn, cs;
    sincosf(ang, &sn, &cs);

    if (hh < NH) {
        size_t base = ((size_t)(b * SEQ + s) * NH + hh) * HD;
        float x0 = g_qraw[base + i] * 0.0625f;
        float x1 = g_qraw[base + i + HALF] * 0.0625f;
        float y0 = x0 * cs - x1 * sn;
        float y1 = x1 * cs + x0 * sn;
        size_t ob = ((size_t)(b * NH + hh) * SEQ + s) * HD;
        fp16 h0 = __float2half_rn(y0);
        qh[ob + i] = h0; ql[ob + i] = __float2half_rn(y0 - __half2float(h0));
        fp16 h1 = __float2half_rn(y1);
        qh[ob + i + HALF] = h1; ql[ob + i + HALF] = __float2half_rn(y1 - __half2float(h1));
    } else {
        size_t base = (size_t)(b * SEQ + s) * HD;
        float x0 = g_kraw[base + i];
        float x1 = g_kraw[base + i + HALF];
        k[base + i]        = __float2half_rn(x0 * cs - x1 * sn);
        k[base + i + HALF] = __float2half_rn(x1 * cs + x0 * sn);
    }
}

// ---------------------------------------------------------------------------
// Causal softmax in place + fp16 hi/lo planes (planes written only up to
// ceil((q+1)/128)*128 — exactly the span PV's causal K-limit reads).
// ---------------------------------------------------------------------------
__global__ __launch_bounds__(256) void softmax_causal_split(
    float* __restrict__ attn, fp16* __restrict__ ah, fp16* __restrict__ al)
{
    __shared__ float sm[SEQ];
    __shared__ float red[256];
    size_t row = blockIdx.x;
    int q = (int)(row % SEQ);
    float* r  = attn + row * SEQ;
    fp16*  rh = ah   + row * SEQ;
    fp16*  rl = al   + row * SEQ;
    int n = q + 1;
    int lim = ((q >> 7) + 1) << 7;          // PV reads cols [0, lim)
    int tid = threadIdx.x;

    float mx = -3.4e38f;
    for (int j = tid; j < n; j += 256) { float v = r[j]; sm[j] = v; mx = fmaxf(mx, v); }
    red[tid] = mx; __syncthreads();
    for (int s = 128; s > 0; s >>= 1) { if (tid < s) red[tid] = fmaxf(red[tid], red[tid + s]); __syncthreads(); }
    mx = red[0];
    __syncthreads();

    float sum = 0.f;
    for (int j = tid; j < n; j += 256) { float e = expf(sm[j] - mx); sm[j] = e; sum += e; }
    red[tid] = sum; __syncthreads();
    for (int s = 128; s > 0; s >>= 1) { if (tid < s) red[tid] += red[tid + s]; __syncthreads(); }
    float inv = 1.f / red[0];

    for (int j = tid; j < SEQ; j += 256) {
        float o = (j < n) ? sm[j] * inv : 0.f;
        r[j] = o;
        if (j < lim) {
            fp16 hb = __float2half_rn(o);
            rh[j] = hb;
            rl[j] = __float2half_rn(o - __half2float(hb));
        }
    }
}

// ---------------------------------------------------------------------------
// Host launcher
// ---------------------------------------------------------------------------
extern "C" void kernel_launch(void* const* d_in, const int* in_sizes, int n_in,
                              void* d_out, int out_size)
{
    const float* hidden = (const float*)d_in[0];
    const float* Wq     = (const float*)d_in[1];
    const float* Wk     = (const float*)d_in[2];
    const float* Wv     = (const float*)d_in[3];
    const float* Wo     = (const float*)d_in[4];
    const int*   pos    = (const int*)d_in[6];

    float *qraw, *kraw, *attn_s;
    fp16 *hid, *wq, *wkv, *wo;
    fp16 *q_h, *q_l, *k, *v, *at_h, *at_l, *ah;

    cudaGetSymbolAddress((void**)&qraw, g_qraw);
    cudaGetSymbolAddress((void**)&kraw, g_kraw);
    cudaGetSymbolAddress((void**)&attn_s, g_attn_s);
    cudaGetSymbolAddress((void**)&hid, g_hid);
    cudaGetSymbolAddress((void**)&wq,  g_wq);
    cudaGetSymbolAddress((void**)&wkv, g_wkv);
    cudaGetSymbolAddress((void**)&wo,  g_wo);
    cudaGetSymbolAddress((void**)&q_h, g_q_h);  cudaGetSymbolAddress((void**)&q_l, g_q_l);
    cudaGetSymbolAddress((void**)&k,   g_k);
    cudaGetSymbolAddress((void**)&v,   g_v);
    cudaGetSymbolAddress((void**)&at_h, g_at_h); cudaGetSymbolAddress((void**)&at_l, g_at_l);
    cudaGetSymbolAddress((void**)&ah,  g_ah);

    float* out = (float*)d_out;
    const long long OUTE  = (long long)BDIM * SEQ * HID;
    const long long ATTNE = (long long)BDIM * NH * SEQ * SEQ;
    float* attn = ((long long)out_size >= OUTE + ATTNE) ? (out + OUTE) : attn_s;

    const int M = BDIM * SEQ;  // 4096

    const int SMEM_NN = STAGES * (2 * BM * (BK + 8) + BK * (BN + 8)) * 2;  // 87,552
    const int SMEM_NT = STAGES * (3 * BM * (BK + 8)) * 2;                  // 92,160
    cudaFuncSetAttribute(gemm2p<false>, cudaFuncAttributeMaxDynamicSharedMemorySize, SMEM_NN);
    cudaFuncSetAttribute(gemm2p<true>,  cudaFuncAttributeMaxDynamicSharedMemorySize, SMEM_NT);

    // input conversions (all to single fp16)
    { int n = BDIM*SEQ*HID; convW<<<(n+255)/256, 256>>>(hidden, hid, HID, HID, 0, n); }
    { int n = HID*NH*HD; convW<<<(n+255)/256, 256>>>(Wq, wq,  NH*HD, NH*HD, 0,  n); }
    { int n = HID*HD;    convW<<<(n+255)/256, 256>>>(Wk, wkv, HD,    2*HD,  0,  n); }
    { int n = HID*HD;    convW<<<(n+255)/256, 256>>>(Wv, wkv, HD,    2*HD,  HD, n); }
    { int n = NH*HD*HID; convW<<<(n+255)/256, 256>>>(Wo, wo,  HID,   HID,   0,  n); }

    // Q projection (single-pass) -> qraw f32
    gemm2p<false><<<dim3(HID/BN, M/BM, 1), 256, SMEM_NN>>>(
        hid, nullptr, wq, qraw, nullptr, nullptr,
        HID, HID, NH*HD, HID, 1, 0,0,0,0,0,0, 0, 0);

    // K|V projection (single-pass, merged N=512): k->f32 kraw, v->fp16
    gemm2p<false><<<dim3(2*HD/BN, M/BM, 1), 256, SMEM_NN>>>(
        hid, nullptr, wkv, kraw, v, nullptr,
        HID, HID, 2*HD, HD, 1, 0,0,0,0,0,0, 0, 2);

    // RoPE + splits
    { int TOT = BDIM*SEQ*(NH+1)*HALF; rope_split<<<(TOT+255)/256, 256>>>(pos, q_h, q_l, k); }

    // scores = q @ k^T (2-pass on q), causal tile skip -> attn f32
    gemm2p<true><<<dim3(SEQ/BN, SEQ/BM, BDIM*NH), 256, SMEM_NT>>>(
        q_h, q_l, k, attn, nullptr, nullptr,
        HD, HD, HD, SEQ,
        NH,
        (long long)NH*SEQ*HD, (long long)SEQ*HD,
        (long long)SEQ*HD, 0,
        (long long)NH*SEQ*SEQ, (long long)SEQ*SEQ,
        1, 0);

    // softmax + attn planes (trimmed to causal span)
    softmax_causal_split<<<BDIM*NH*SEQ, 256>>>(attn, at_h, at_l);

    // PV (2-pass on attn) -> single fp16 ah, causal K-limit
    gemm2p<false><<<dim3(HD/BN, SEQ/BM, BDIM*NH), 256, SMEM_NN>>>(
        at_h, at_l, v, nullptr, ah, nullptr,
        SEQ, SEQ, HD, NH*HD,
        NH,
        (long long)NH*SEQ*SEQ, (long long)SEQ*SEQ,
        (long long)SEQ*HD, 0,
        (long long)SEQ*NH*HD, (long long)HD,
        2, 3);

    // out = ah @ Wo (single-pass)
    gemm2p<false><<<dim3(HID/BN, M/BM, 1), 256, SMEM_NN>>>(
        ah, nullptr, wo, out, nullptr, nullptr,
        NH*HD, NH*HD, HID, HID, 1, 0,0,0,0,0,0, 0, 0);
}

// round 11
// speedup vs baseline: 4.9896x; 1.0696x over previous
#include <cuda_runtime.h>
#include <cuda_fp16.h>
#include <math.h>
#include <stdint.h>

#define BDIM 2
#define SEQ  2048
#define HID  2048
#define NH   8
#define HD   256
#define HALF 128

#define BM 128
#define BN 128
#define BK 32
#define STAGES 3

typedef __half fp16;

// ------------------------- static device scratch ---------------------------
__device__ __align__(16) float g_qraw[BDIM*SEQ*NH*HD];
__device__ __align__(16) float g_kraw[BDIM*SEQ*HD];
__device__ __align__(16) float g_attn_s[(size_t)BDIM*NH*SEQ*SEQ];

__device__ __align__(16) fp16 g_hid[BDIM*SEQ*HID];
__device__ __align__(16) fp16 g_wqkv[HID*(NH*HD + 2*HD)];  // [2048, 2560] Wq|Wk|Wv
__device__ __align__(16) fp16 g_wo[NH*HD*HID];             // [2048, 2048]
__device__ __align__(16) fp16 g_q[BDIM*NH*SEQ*HD];         // single fp16
__device__ __align__(16) fp16 g_k[BDIM*SEQ*HD];
__device__ __align__(16) fp16 g_v[BDIM*SEQ*HD];
__device__ __align__(16) fp16 g_at_h[(size_t)BDIM*NH*SEQ*SEQ];
__device__ __align__(16) fp16 g_at_l[(size_t)BDIM*NH*SEQ*SEQ];
__device__ __align__(16) fp16 g_ah[BDIM*SEQ*NH*HD];

// ------------------------------- helpers -----------------------------------
__device__ __forceinline__ uint32_t smem_u32(const void* p) {
    return (uint32_t)__cvta_generic_to_shared(p);
}
__device__ __forceinline__ void cp16a(void* dst, const void* src) {
    asm volatile("cp.async.cg.shared.global [%0], [%1], 16;\n"
                 :: "r"(smem_u32(dst)), "l"(src));
}
__device__ __forceinline__ void cp_commit() { asm volatile("cp.async.commit_group;\n"); }
template<int N> __device__ __forceinline__ void cp_wait() {
    asm volatile("cp.async.wait_group %0;\n" :: "n"(N));
}
__device__ __forceinline__ void ldm4(uint32_t r[4], uint32_t a) {
    asm volatile("ldmatrix.sync.aligned.m8n8.x4.shared.b16 {%0,%1,%2,%3}, [%4];\n"
                 : "=r"(r[0]), "=r"(r[1]), "=r"(r[2]), "=r"(r[3]) : "r"(a));
}
__device__ __forceinline__ void ldm4t(uint32_t r[4], uint32_t a) {
    asm volatile("ldmatrix.sync.aligned.m8n8.x4.trans.shared.b16 {%0,%1,%2,%3}, [%4];\n"
                 : "=r"(r[0]), "=r"(r[1]), "=r"(r[2]), "=r"(r[3]) : "r"(a));
}
__device__ __forceinline__ void mma_fp16(float c[4], const uint32_t a[4],
                                         uint32_t b0, uint32_t b1) {
    asm volatile(
        "mma.sync.aligned.m16n8k16.row.col.f32.f16.f16.f32 "
        "{%0,%1,%2,%3}, {%4,%5,%6,%7}, {%8,%9}, {%0,%1,%2,%3};\n"
        : "+f"(c[0]), "+f"(c[1]), "+f"(c[2]), "+f"(c[3])
        : "r"(a[0]), "r"(a[1]), "r"(a[2]), "r"(a[3]), "r"(b0), "r"(b1));
}
__device__ __forceinline__ uint32_t pack2h(float a, float b) {
    __half2 v = __floats2half2_rn(a, b);
    return *(uint32_t*)&v;
}

// ---------------------------------------------------------------------------
// fp16 GEMM, optional 2nd MMA pass with A-lo plane (Al may be nullptr).
// C = (Ah [+Al])[M,K] @ B.
// NT=false: B [K,N] row-major.  NT=true: B [N,K] row-major (C = A·B^T).
// epi: 0 f32 C (ldc); 1 fp16 hi/lo Ch/Cl (ldc); 3 fp16 single Ch (ldc);
//      4 QKV triple: n0<2048 -> f32 C (ldc 2048); n0 in [2048,2304) -> f32 C2
//        (ldc 256); n0>=2304 -> fp16 Ch (ldc 256).
// cmode: 0 none; 1 (NT) causal tile-skip; 2 causal K-limit.
// 256 threads, warps 2(m) x 4(n), warp tile 64x32, 3-stage cp.async.
// SMEM layout is compact: B plane follows A-hi when Al == nullptr.
// ---------------------------------------------------------------------------
template<bool NT>
__global__ __launch_bounds__(256, 2) void gemm2p(
    const fp16* __restrict__ Ah, const fp16* __restrict__ Al,
    const fp16* __restrict__ Bs,
    float* __restrict__ C, float* __restrict__ C2,
    fp16* __restrict__ Ch, fp16* __restrict__ Cl,
    int K, int lda, int ldb, int ldc,
    int zdiv, long long Ao, long long Ai, long long Bo, long long Bi,
    long long Co, long long Ci, int cmode, int epi)
{
    if (NT && cmode == 1 && blockIdx.x > blockIdx.y) return;

    constexpr int ASTR  = BK + 8;                  // 40
    constexpr int BROWS = NT ? BN : BK;
    constexpr int BSTR  = NT ? (BK + 8) : (BN + 8);
    constexpr int AELEM = BM * ASTR;               // 5120
    constexpr int BELEM = BROWS * BSTR;

    extern __shared__ fp16 smem[];
    const bool has_lo = (Al != nullptr);
    fp16* pAh = smem;
    fp16* pAl = pAh + STAGES * AELEM;
    fp16* pB  = has_lo ? (pAl + STAGES * AELEM) : pAl;

    int z = blockIdx.z;
    int zo = z / zdiv, zi = z - zo * zdiv;
    Ah += zo * Ao + zi * Ai;
    if (has_lo) Al += zo * Ao + zi * Ai;
    Bs += zo * Bo + zi * Bi;
    long long coff = zo * Co + zi * Ci;

    int m0 = blockIdx.y * BM, n0 = blockIdx.x * BN;
    int tid = threadIdx.x, lane = tid & 31, wid = tid >> 5;
    int wm = wid & 1, wn = wid >> 1;

    int kmax = (cmode == 2) ? min(K, m0 + BM) : K;
    int niter = kmax / BK;

    const int ar0 = tid >> 2,         ac0 = (tid & 3) * 8;
    const int ar1 = (tid + 256) >> 2, ac1 = ac0;
    const int br0 = tid >> 4,         bc0 = (tid & 15) * 8;
    const int br1 = (tid + 256) >> 4, bc1 = bc0;

    float c[4][4][4];
#pragma unroll
    for (int mt = 0; mt < 4; mt++)
#pragma unroll
        for (int nt = 0; nt < 4; nt++)
#pragma unroll
            for (int i = 0; i < 4; i++) c[mt][nt][i] = 0.f;

    auto load_stage = [&](int st, int k0) {
        fp16* ah = pAh + st * AELEM;  fp16* al = pAl + st * AELEM;
        fp16* bb = pB  + st * BELEM;
        cp16a(ah + ar0 * ASTR + ac0, Ah + (size_t)(m0 + ar0) * lda + k0 + ac0);
        cp16a(ah + ar1 * ASTR + ac1, Ah + (size_t)(m0 + ar1) * lda + k0 + ac1);
        if (has_lo) {
            cp16a(al + ar0 * ASTR + ac0, Al + (size_t)(m0 + ar0) * lda + k0 + ac0);
            cp16a(al + ar1 * ASTR + ac1, Al + (size_t)(m0 + ar1) * lda + k0 + ac1);
        }
        if (NT) {
            cp16a(bb + ar0 * BSTR + ac0, Bs + (size_t)(n0 + ar0) * ldb + k0 + ac0);
            cp16a(bb + ar1 * BSTR + ac1, Bs + (size_t)(n0 + ar1) * ldb + k0 + ac1);
        } else {
            cp16a(bb + br0 * BSTR + bc0, Bs + (size_t)(k0 + br0) * ldb + n0 + bc0);
            cp16a(bb + br1 * BSTR + bc1, Bs + (size_t)(k0 + br1) * ldb + n0 + bc1);
        }
    };

#pragma unroll
    for (int s = 0; s < STAGES - 1; s++) {
        if (s < niter) load_stage(s, s * BK);
        cp_commit();
    }

    for (int it = 0; it < niter; it++) {
        cp_wait<STAGES - 2>();
        __syncthreads();

        int nk = it + STAGES - 1;
        if (nk < niter) load_stage(nk % STAGES, nk * BK);
        cp_commit();

        int st = it % STAGES;
        const fp16* ah = pAh + st * AELEM;
        const fp16* al = pAl + st * AELEM;
        const fp16* bb = pB  + st * BELEM;

#pragma unroll
        for (int ks = 0; ks < BK; ks += 16) {
            uint32_t fa[4][4], fb[8];
#pragma unroll
            for (int mt = 0; mt < 4; mt++) {
                int row = wm * 64 + mt * 16 + (lane & 15);
                int col = ks + ((lane >> 4) << 3);
                ldm4(fa[mt], smem_u32(ah + row * ASTR + col));
            }
#pragma unroll
            for (int p = 0; p < 2; p++) {
                if (NT) {
                    int row = wn * 32 + p * 16 + (lane & 7) + ((lane >> 4) << 3);
                    int col = ks + (lane & 8);
                    ldm4(&fb[4 * p], smem_u32(bb + row * BSTR + col));
                } else {
                    int row = ks + (lane & 15);
                    int col = wn * 32 + p * 16 + ((lane >> 4) << 3);
                    ldm4t(&fb[4 * p], smem_u32(bb + row * BSTR + col));
                }
            }
#pragma unroll
            for (int mt = 0; mt < 4; mt++)
#pragma unroll
                for (int nt = 0; nt < 4; nt++)
                    mma_fp16(c[mt][nt], fa[mt], fb[2*nt], fb[2*nt+1]);
            if (has_lo) {
#pragma unroll
                for (int mt = 0; mt < 4; mt++) {
                    int row = wm * 64 + mt * 16 + (lane & 15);
                    int col = ks + ((lane >> 4) << 3);
                    ldm4(fa[mt], smem_u32(al + row * ASTR + col));
                }
#pragma unroll
                for (int mt = 0; mt < 4; mt++)
#pragma unroll
                    for (int nt = 0; nt < 4; nt++)
                        mma_fp16(c[mt][nt], fa[mt], fb[2*nt], fb[2*nt+1]);
            }
        }
        __syncthreads();
    }

    // ---- epilogue ----
    int mode = epi;
    int nbase = n0;
    int ld = ldc;
    float* Cf = C;
    if (epi == 4) {
        if (n0 < 2048)      { mode = 0; ld = 2048; }
        else if (n0 < 2304) { mode = 0; Cf = C2; ld = 256; nbase = n0 - 2048; }
        else                { mode = 3; ld = 256; nbase = n0 - 2304; }
    }
#pragma unroll
    for (int mt = 0; mt < 4; mt++)
#pragma unroll
        for (int nt = 0; nt < 4; nt++) {
            int row = m0 + wm * 64 + mt * 16 + (lane >> 2);
            int col = nbase + wn * 32 + nt * 8 + (lane & 3) * 2;
            size_t o0 = (size_t)coff + (size_t)row * ld + col;
            size_t o1 = (size_t)coff + (size_t)(row + 8) * ld + col;
            float f0 = c[mt][nt][0], f1 = c[mt][nt][1];
            float f2 = c[mt][nt][2], f3 = c[mt][nt][3];
            if (mode == 0) {
                *(float2*)(Cf + o0) = make_float2(f0, f1);
                *(float2*)(Cf + o1) = make_float2(f2, f3);
            } else if (mode == 1) {
                fp16 h0 = __float2half_rn(f0), h1 = __float2half_rn(f1);
                fp16 h2 = __float2half_rn(f2), h3 = __float2half_rn(f3);
                *(uint32_t*)(Ch + o0) = pack2h(f0, f1);
                *(uint32_t*)(Ch + o1) = pack2h(f2, f3);
                *(uint32_t*)(Cl + o0) = pack2h(f0 - __half2float(h0), f1 - __half2float(h1));
                *(uint32_t*)(Cl + o1) = pack2h(f2 - __half2float(h2), f3 - __half2float(h3));
            } else {  // mode 3
                *(uint32_t*)(Ch + o0) = pack2h(f0, f1);
                *(uint32_t*)(Ch + o1) = pack2h(f2, f3);
            }
        }
}

// ---------------------------------------------------------------------------
// All 5 input conversions in one kernel (region-dispatched by flat index).
// hidden -> hid; Wq -> wqkv[:, 0:2048]; Wk -> wqkv[:, 2048:2304];
// Wv -> wqkv[:, 2304:2560]; Wo -> wo.
// ---------------------------------------------------------------------------
#define CVN0 (BDIM*SEQ*HID)       // 8388608
#define CVN1 (HID*NH*HD)          // 4194304
#define CVN2 (HID*HD)             // 524288
#define CVTOT (CVN0 + CVN1 + 2*CVN2 + CVN1)

__global__ void conv_all(const float* __restrict__ hidden,
                         const float* __restrict__ Wq, const float* __restrict__ Wk,
                         const float* __restrict__ Wv, const float* __restrict__ Wo,
                         fp16* __restrict__ hid, fp16* __restrict__ wqkv,
                         fp16* __restrict__ wo)
{
    int i = blockIdx.x * 256 + threadIdx.x;
    if (i < CVN0) { hid[i] = __float2half_rn(hidden[i]); return; }
    i -= CVN0;
    if (i < CVN1) {
        int r = i >> 11, ccol = i & 2047;
        wqkv[(size_t)r * 2560 + ccol] = __float2half_rn(Wq[i]);
        return;
    }
    i -= CVN1;
    if (i < CVN2) {
        int r = i >> 8, ccol = i & 255;
        wqkv[(size_t)r * 2560 + 2048 + ccol] = __float2half_rn(Wk[i]);
        return;
    }
    i -= CVN2;
    if (i < CVN2) {
        int r = i >> 8, ccol = i & 255;
        wqkv[(size_t)r * 2560 + 2304 + ccol] = __float2half_rn(Wv[i]);
        return;
    }
    i -= CVN2;
    if (i < CVN1) wo[i] = __float2half_rn(Wo[i]);
}

// ---------------------------------------------------------------------------
// RoPE: qraw [B,S,H,D] -> q single fp16 [B,H,S,D] (scaled 1/16);
//       kraw [B,S,D]   -> k single fp16 [B,S,D]
// ---------------------------------------------------------------------------
__global__ void rope_conv(const int* __restrict__ pos,
                          fp16* __restrict__ q, fp16* __restrict__ k)
{
    int t = blockIdx.x * 256 + threadIdx.x;
    const int TOT = BDIM * SEQ * (NH + 1) * HALF;
    if (t >= TOT) return;
    int i = t & (HALF - 1);
    int rest = t >> 7;
    int hh = rest % (NH + 1); rest /= (NH + 1);
    int s = rest % SEQ;
    int b = rest / SEQ;

    float p = (float)pos[b * SEQ + s];
    float freq = powf(10000.f, -(float)(2 * i) / (float)HD);
    float ang = p * freq;
    float sn, cs;
    sincosf(ang, &sn, &cs);

    if (hh < NH) {
        size_t base = ((size_t)(b * SEQ + s) * NH + hh) * HD;
        float x0 = g_qraw[base + i] * 0.0625f;
        float x1 = g_qraw[base + i + HALF] * 0.0625f;
        size_t ob = ((size_t)(b * NH + hh) * SEQ + s) * HD;
        q[ob + i]        = __float2half_rn(x0 * cs - x1 * sn);
        q[ob + i + HALF] = __float2half_rn(x1 * cs + x0 * sn);
    } else {
        size_t base = (size_t)(b * SEQ + s) * HD;
        float x0 = g_kraw[base + i];
        float x1 = g_kraw[base + i + HALF];
        k[base + i]        = __float2half_rn(x0 * cs - x1 * sn);
        k[base + i + HALF] = __float2half_rn(x1 * cs + x0 * sn);
    }
}

// ---------------------------------------------------------------------------
// Causal softmax in place + fp16 hi/lo planes (trimmed to PV's causal span).
// ---------------------------------------------------------------------------
__global__ __launch_bounds__(256) void softmax_causal_split(
    float* __restrict__ attn, fp16* __restrict__ ah, fp16* __restrict__ al)
{
    __shared__ float sm[SEQ];
    __shared__ float red[256];
    size_t row = blockIdx.x;
    int q = (int)(row % SEQ);
    float* r  = attn + row * SEQ;
    fp16*  rh = ah   + row * SEQ;
    fp16*  rl = al   + row * SEQ;
    int n = q + 1;
    int lim = ((q >> 7) + 1) << 7;
    int tid = threadIdx.x;

    float mx = -3.4e38f;
    for (int j = tid; j < n; j += 256) { float v = r[j]; sm[j] = v; mx = fmaxf(mx, v); }
    red[tid] = mx; __syncthreads();
    for (int s = 128; s > 0; s >>= 1) { if (tid < s) red[tid] = fmaxf(red[tid], red[tid + s]); __syncthreads(); }
    mx = red[0];
    __syncthreads();

    float sum = 0.f;
    for (int j = tid; j < n; j += 256) { float e = expf(sm[j] - mx); sm[j] = e; sum += e; }
    red[tid] = sum; __syncthreads();
    for (int s = 128; s > 0; s >>= 1) { if (tid < s) red[tid] += red[tid + s]; __syncthreads(); }
    float inv = 1.f / red[0];

    for (int j = tid; j < SEQ; j += 256) {
        float o = (j < n) ? sm[j] * inv : 0.f;
        r[j] = o;
        if (j < lim) {
            fp16 hb = __float2half_rn(o);
            rh[j] = hb;
            rl[j] = __float2half_rn(o - __half2float(hb));
        }
    }
}

// ---------------------------------------------------------------------------
// Host launcher
// ---------------------------------------------------------------------------
extern "C" void kernel_launch(void* const* d_in, const int* in_sizes, int n_in,
                              void* d_out, int out_size)
{
    const float* hidden = (const float*)d_in[0];
    const float* Wq     = (const float*)d_in[1];
    const float* Wk     = (const float*)d_in[2];
    const float* Wv     = (const float*)d_in[3];
    const float* Wo     = (const float*)d_in[4];
    const int*   pos    = (const int*)d_in[6];

    float *qraw, *kraw, *attn_s;
    fp16 *hid, *wqkv, *wo, *q, *k, *v, *at_h, *at_l, *ah;

    cudaGetSymbolAddress((void**)&qraw, g_qraw);
    cudaGetSymbolAddress((void**)&kraw, g_kraw);
    cudaGetSymbolAddress((void**)&attn_s, g_attn_s);
    cudaGetSymbolAddress((void**)&hid, g_hid);
    cudaGetSymbolAddress((void**)&wqkv, g_wqkv);
    cudaGetSymbolAddress((void**)&wo,  g_wo);
    cudaGetSymbolAddress((void**)&q,   g_q);
    cudaGetSymbolAddress((void**)&k,   g_k);
    cudaGetSymbolAddress((void**)&v,   g_v);
    cudaGetSymbolAddress((void**)&at_h, g_at_h);
    cudaGetSymbolAddress((void**)&at_l, g_at_l);
    cudaGetSymbolAddress((void**)&ah,  g_ah);

    float* out = (float*)d_out;
    const long long OUTE  = (long long)BDIM * SEQ * HID;
    const long long ATTNE = (long long)BDIM * NH * SEQ * SEQ;
    float* attn = ((long long)out_size >= OUTE + ATTNE) ? (out + OUTE) : attn_s;

    const int M = BDIM * SEQ;  // 4096

    // smem sizes (bytes): A-hi [+A-lo] + B
    const int AEL = BM * (BK + 8);            // 5120 elems
    const int BEL_NN = BK * (BN + 8);         // 4352 elems
    const int SM_NN1 = STAGES * (AEL + BEL_NN) * 2;        // 56832  (single-pass NN)
    const int SM_NN2 = STAGES * (2 * AEL + BEL_NN) * 2;    // 87552  (2-pass NN)
    const int SM_NT1 = STAGES * (2 * AEL) * 2;             // 61440  (single-pass NT)
    cudaFuncSetAttribute(gemm2p<false>, cudaFuncAttributeMaxDynamicSharedMemorySize, SM_NN2);
    cudaFuncSetAttribute(gemm2p<true>,  cudaFuncAttributeMaxDynamicSharedMemorySize, SM_NT1);

    // 1: all conversions
    conv_all<<<(CVTOT + 255) / 256, 256>>>(hidden, Wq, Wk, Wv, Wo, hid, wqkv, wo);

    // 2: merged QKV projection (single-pass, N=2560)
    gemm2p<false><<<dim3(2560/BN, M/BM, 1), 256, SM_NN1>>>(
        hid, nullptr, wqkv, qraw, kraw, v, nullptr,
        HID, HID, 2560, HID, 1, 0,0,0,0,0,0, 0, 4);

    // 3: RoPE
    { int TOT = BDIM*SEQ*(NH+1)*HALF; rope_conv<<<(TOT+255)/256, 256>>>(pos, q, k); }

    // 4: scores = q @ k^T (single-pass), causal tile skip -> attn f32
    gemm2p<true><<<dim3(SEQ/BN, SEQ/BM, BDIM*NH), 256, SM_NT1>>>(
        q, nullptr, k, attn, nullptr, nullptr, nullptr,
        HD, HD, HD, SEQ,
        NH,
        (long long)NH*SEQ*HD, (long long)SEQ*HD,
        (long long)SEQ*HD, 0,
        (long long)NH*SEQ*SEQ, (long long)SEQ*SEQ,
        1, 0);

    // 5: softmax + attn planes
    softmax_causal_split<<<BDIM*NH*SEQ, 256>>>(attn, at_h, at_l);

    // 6: PV (2-pass on attn planes) -> single fp16 ah, causal K-limit
    gemm2p<false><<<dim3(HD/BN, SEQ/BM, BDIM*NH), 256, SM_NN2>>>(
        at_h, at_l, v, nullptr, nullptr, ah, nullptr,
        SEQ, SEQ, HD, NH*HD,
        NH,
        (long long)NH*SEQ*SEQ, (long long)SEQ*SEQ,
        (long long)SEQ*HD, 0,
        (long long)SEQ*NH*HD, (long long)HD,
        2, 3);

    // 7: out = ah @ Wo (single-pass)
    gemm2p<false><<<dim3(HID/BN, M/BM, 1), 256, SM_NN1>>>(
        ah, nullptr, wo, out, nullptr, nullptr, nullptr,
        NH*HD, NH*HD, HID, HID, 1, 0,0,0,0,0,0, 0, 0);
}

// round 13
// speedup vs baseline: 5.8230x; 1.1670x over previous
#include <cuda_runtime.h>
#include <cuda_fp16.h>
#include <math.h>
#include <stdint.h>

#define BDIM 2
#define SEQ  2048
#define HID  2048
#define NH   8
#define HD   256
#define HALF 128

#define BM 128
#define BN 128
#define BK 32
#define STAGES 3

typedef __half fp16;

// ------------------------- static device scratch ---------------------------
__device__ __align__(16) float g_qraw[BDIM*SEQ*NH*HD];
__device__ __align__(16) float g_kraw[BDIM*SEQ*HD];
__device__ __align__(16) float g_attn_s[(size_t)BDIM*NH*SEQ*SEQ];

__device__ __align__(16) fp16 g_hid[BDIM*SEQ*HID];
__device__ __align__(16) fp16 g_wqkv[HID*(NH*HD + 2*HD)];  // [2048, 2560] Wq|Wk|Wv
__device__ __align__(16) fp16 g_wo[NH*HD*HID];             // [2048, 2048]
__device__ __align__(16) fp16 g_q[BDIM*NH*SEQ*HD];
__device__ __align__(16) fp16 g_k[BDIM*SEQ*HD];
__device__ __align__(16) fp16 g_v[BDIM*SEQ*HD];
__device__ __align__(16) fp16 g_at[(size_t)BDIM*NH*SEQ*SEQ];   // single fp16 attn
__device__ __align__(16) fp16 g_ah[BDIM*SEQ*NH*HD];

// ------------------------------- helpers -----------------------------------
__device__ __forceinline__ uint32_t smem_u32(const void* p) {
    return (uint32_t)__cvta_generic_to_shared(p);
}
__device__ __forceinline__ void cp16a(void* dst, const void* src) {
    asm volatile("cp.async.cg.shared.global [%0], [%1], 16;\n"
                 :: "r"(smem_u32(dst)), "l"(src));
}
__device__ __forceinline__ void cp_commit() { asm volatile("cp.async.commit_group;\n"); }
template<int N> __device__ __forceinline__ void cp_wait() {
    asm volatile("cp.async.wait_group %0;\n" :: "n"(N));
}
__device__ __forceinline__ void ldm4(uint32_t r[4], uint32_t a) {
    asm volatile("ldmatrix.sync.aligned.m8n8.x4.shared.b16 {%0,%1,%2,%3}, [%4];\n"
                 : "=r"(r[0]), "=r"(r[1]), "=r"(r[2]), "=r"(r[3]) : "r"(a));
}
__device__ __forceinline__ void ldm4t(uint32_t r[4], uint32_t a) {
    asm volatile("ldmatrix.sync.aligned.m8n8.x4.trans.shared.b16 {%0,%1,%2,%3}, [%4];\n"
                 : "=r"(r[0]), "=r"(r[1]), "=r"(r[2]), "=r"(r[3]) : "r"(a));
}
__device__ __forceinline__ void mma_fp16(float c[4], const uint32_t a[4],
                                         uint32_t b0, uint32_t b1) {
    asm volatile(
        "mma.sync.aligned.m16n8k16.row.col.f32.f16.f16.f32 "
        "{%0,%1,%2,%3}, {%4,%5,%6,%7}, {%8,%9}, {%0,%1,%2,%3};\n"
        : "+f"(c[0]), "+f"(c[1]), "+f"(c[2]), "+f"(c[3])
        : "r"(a[0]), "r"(a[1]), "r"(a[2]), "r"(a[3]), "r"(b0), "r"(b1));
}
__device__ __forceinline__ uint32_t pack2h(float a, float b) {
    __half2 v = __floats2half2_rn(a, b);
    return *(uint32_t*)&v;
}

// ---------------------------------------------------------------------------
// fp16 GEMM, optional 2nd MMA pass with A-lo plane (Al may be nullptr).
// C = (Ah [+Al])[M,K] @ B.
// NT=false: B [K,N] row-major.  NT=true: B [N,K] row-major (C = A·B^T).
// epi: 0 f32 C (ldc); 3 fp16 single Ch (ldc);
//      4 QKV triple: n0<2048 -> f32 C (ldc 2048); [2048,2304) -> f32 C2
//        (ldc 256); >=2304 -> fp16 Ch (ldc 256).
// cmode: 0 none; 1 (NT) causal tile-skip; 2 causal K-limit.
// 256 threads, warps 2(m) x 4(n), warp tile 64x32, 3-stage cp.async.
// SMEM layout compact: B plane follows A-hi when Al == nullptr.
// ---------------------------------------------------------------------------
template<bool NT>
__global__ __launch_bounds__(256, 2) void gemm2p(
    const fp16* __restrict__ Ah, const fp16* __restrict__ Al,
    const fp16* __restrict__ Bs,
    float* __restrict__ C, float* __restrict__ C2, fp16* __restrict__ Ch,
    int K, int lda, int ldb, int ldc,
    int zdiv, long long Ao, long long Ai, long long Bo, long long Bi,
    long long Co, long long Ci, int cmode, int epi)
{
    if (NT && cmode == 1 && blockIdx.x > blockIdx.y) return;

    constexpr int ASTR  = BK + 8;                  // 40
    constexpr int BROWS = NT ? BN : BK;
    constexpr int BSTR  = NT ? (BK + 8) : (BN + 8);
    constexpr int AELEM = BM * ASTR;               // 5120
    constexpr int BELEM = BROWS * BSTR;

    extern __shared__ fp16 smem[];
    const bool has_lo = (Al != nullptr);
    fp16* pAh = smem;
    fp16* pAl = pAh + STAGES * AELEM;
    fp16* pB  = has_lo ? (pAl + STAGES * AELEM) : pAl;

    int z = blockIdx.z;
    int zo = z / zdiv, zi = z - zo * zdiv;
    Ah += zo * Ao + zi * Ai;
    if (has_lo) Al += zo * Ao + zi * Ai;
    Bs += zo * Bo + zi * Bi;
    long long coff = zo * Co + zi * Ci;

    int m0 = blockIdx.y * BM, n0 = blockIdx.x * BN;
    int tid = threadIdx.x, lane = tid & 31, wid = tid >> 5;
    int wm = wid & 1, wn = wid >> 1;

    int kmax = (cmode == 2) ? min(K, m0 + BM) : K;
    int niter = kmax / BK;

    const int ar0 = tid >> 2,         ac0 = (tid & 3) * 8;
    const int ar1 = (tid + 256) >> 2, ac1 = ac0;
    const int br0 = tid >> 4,         bc0 = (tid & 15) * 8;
    const int br1 = (tid + 256) >> 4, bc1 = bc0;

    float c[4][4][4];
#pragma unroll
    for (int mt = 0; mt < 4; mt++)
#pragma unroll
        for (int nt = 0; nt < 4; nt++)
#pragma unroll
            for (int i = 0; i < 4; i++) c[mt][nt][i] = 0.f;

    auto load_stage = [&](int st, int k0) {
        fp16* ah = pAh + st * AELEM;  fp16* al = pAl + st * AELEM;
        fp16* bb = pB  + st * BELEM;
        cp16a(ah + ar0 * ASTR + ac0, Ah + (size_t)(m0 + ar0) * lda + k0 + ac0);
        cp16a(ah + ar1 * ASTR + ac1, Ah + (size_t)(m0 + ar1) * lda + k0 + ac1);
        if (has_lo) {
            cp16a(al + ar0 * ASTR + ac0, Al + (size_t)(m0 + ar0) * lda + k0 + ac0);
            cp16a(al + ar1 * ASTR + ac1, Al + (size_t)(m0 + ar1) * lda + k0 + ac1);
        }
        if (NT) {
            cp16a(bb + ar0 * BSTR + ac0, Bs + (size_t)(n0 + ar0) * ldb + k0 + ac0);
            cp16a(bb + ar1 * BSTR + ac1, Bs + (size_t)(n0 + ar1) * ldb + k0 + ac1);
        } else {
            cp16a(bb + br0 * BSTR + bc0, Bs + (size_t)(k0 + br0) * ldb + n0 + bc0);
            cp16a(bb + br1 * BSTR + bc1, Bs + (size_t)(k0 + br1) * ldb + n0 + bc1);
        }
    };

#pragma unroll
    for (int s = 0; s < STAGES - 1; s++) {
        if (s < niter) load_stage(s, s * BK);
        cp_commit();
    }

    for (int it = 0; it < niter; it++) {
        cp_wait<STAGES - 2>();
        __syncthreads();

        int nk = it + STAGES - 1;
        if (nk < niter) load_stage(nk % STAGES, nk * BK);
        cp_commit();

        int st = it % STAGES;
        const fp16* ah = pAh + st * AELEM;
        const fp16* al = pAl + st * AELEM;
        const fp16* bb = pB  + st * BELEM;

#pragma unroll
        for (int ks = 0; ks < BK; ks += 16) {
            uint32_t fa[4][4], fb[8];
#pragma unroll
            for (int mt = 0; mt < 4; mt++) {
                int row = wm * 64 + mt * 16 + (lane & 15);
                int col = ks + ((lane >> 4) << 3);
                ldm4(fa[mt], smem_u32(ah + row * ASTR + col));
            }
#pragma unroll
            for (int p = 0; p < 2; p++) {
                if (NT) {
                    int row = wn * 32 + p * 16 + (lane & 7) + ((lane >> 4) << 3);
                    int col = ks + (lane & 8);
                    ldm4(&fb[4 * p], smem_u32(bb + row * BSTR + col));
                } else {
                    int row = ks + (lane & 15);
                    int col = wn * 32 + p * 16 + ((lane >> 4) << 3);
                    ldm4t(&fb[4 * p], smem_u32(bb + row * BSTR + col));
                }
            }
#pragma unroll
            for (int mt = 0; mt < 4; mt++)
#pragma unroll
                for (int nt = 0; nt < 4; nt++)
                    mma_fp16(c[mt][nt], fa[mt], fb[2*nt], fb[2*nt+1]);
            if (has_lo) {
#pragma unroll
                for (int mt = 0; mt < 4; mt++) {
                    int row = wm * 64 + mt * 16 + (lane & 15);
                    int col = ks + ((lane >> 4) << 3);
                    ldm4(fa[mt], smem_u32(al + row * ASTR + col));
                }
#pragma unroll
                for (int mt = 0; mt < 4; mt++)
#pragma unroll
                    for (int nt = 0; nt < 4; nt++)
                        mma_fp16(c[mt][nt], fa[mt], fb[2*nt], fb[2*nt+1]);
            }
        }
        __syncthreads();
    }

    // ---- epilogue ----
    int mode = epi;
    int nbase = n0;
    int ld = ldc;
    float* Cf = C;
    if (epi == 4) {
        if (n0 < 2048)      { mode = 0; ld = 2048; }
        else if (n0 < 2304) { mode = 0; Cf = C2; ld = 256; nbase = n0 - 2048; }
        else                { mode = 3; ld = 256; nbase = n0 - 2304; }
    }
#pragma unroll
    for (int mt = 0; mt < 4; mt++)
#pragma unroll
        for (int nt = 0; nt < 4; nt++) {
            int row = m0 + wm * 64 + mt * 16 + (lane >> 2);
            int col = nbase + wn * 32 + nt * 8 + (lane & 3) * 2;
            size_t o0 = (size_t)coff + (size_t)row * ld + col;
            size_t o1 = (size_t)coff + (size_t)(row + 8) * ld + col;
            float f0 = c[mt][nt][0], f1 = c[mt][nt][1];
            float f2 = c[mt][nt][2], f3 = c[mt][nt][3];
            if (mode == 0) {
                *(float2*)(Cf + o0) = make_float2(f0, f1);
                *(float2*)(Cf + o1) = make_float2(f2, f3);
            } else {  // mode 3: fp16 single
                *(uint32_t*)(Ch + o0) = pack2h(f0, f1);
                *(uint32_t*)(Ch + o1) = pack2h(f2, f3);
            }
        }
}

// ---------------------------------------------------------------------------
// All 5 input conversions in one kernel (region-dispatched by flat index).
// ---------------------------------------------------------------------------
#define CVN0 (BDIM*SEQ*HID)       // 8388608
#define CVN1 (HID*NH*HD)          // 4194304
#define CVN2 (HID*HD)             // 524288
#define CVTOT (CVN0 + CVN1 + 2*CVN2 + CVN1)

__global__ void conv_all(const float* __restrict__ hidden,
                         const float* __restrict__ Wq, const float* __restrict__ Wk,
                         const float* __restrict__ Wv, const float* __restrict__ Wo,
                         fp16* __restrict__ hid, fp16* __restrict__ wqkv,
                         fp16* __restrict__ wo)
{
    int i = blockIdx.x * 256 + threadIdx.x;
    if (i < CVN0) { hid[i] = __float2half_rn(hidden[i]); return; }
    i -= CVN0;
    if (i < CVN1) {
        int r = i >> 11, ccol = i & 2047;
        wqkv[(size_t)r * 2560 + ccol] = __float2half_rn(Wq[i]);
        return;
    }
    i -= CVN1;
    if (i < CVN2) {
        int r = i >> 8, ccol = i & 255;
        wqkv[(size_t)r * 2560 + 2048 + ccol] = __float2half_rn(Wk[i]);
        return;
    }
    i -= CVN2;
    if (i < CVN2) {
        int r = i >> 8, ccol = i & 255;
        wqkv[(size_t)r * 2560 + 2304 + ccol] = __float2half_rn(Wv[i]);
        return;
    }
    i -= CVN2;
    if (i < CVN1) wo[i] = __float2half_rn(Wo[i]);
}

// ---------------------------------------------------------------------------
// RoPE: qraw [B,S,H,D] -> q fp16 [B,H,S,D] (scaled 1/16); kraw -> k fp16
// ---------------------------------------------------------------------------
__global__ void rope_conv(const int* __restrict__ pos,
                          fp16* __restrict__ q, fp16* __restrict__ k)
{
    int t = blockIdx.x * 256 + threadIdx.x;
    const int TOT = BDIM * SEQ * (NH + 1) * HALF;
    if (t >= TOT) return;
    int i = t & (HALF - 1);
    int rest = t >> 7;
    int hh = rest % (NH + 1); rest /= (NH + 1);
    int s = rest % SEQ;
    int b = rest / SEQ;

    float p = (float)pos[b * SEQ + s];
    float freq = powf(10000.f, -(float)(2 * i) / (float)HD);
    float ang = p * freq;
    float sn, cs;
    sincosf(ang, &sn, &cs);

    if (hh < NH) {
        size_t base = ((size_t)(b * SEQ + s) * NH + hh) * HD;
        float x0 = g_qraw[base + i] * 0.0625f;
        float x1 = g_qraw[base + i + HALF] * 0.0625f;
        size_t ob = ((size_t)(b * NH + hh) * SEQ + s) * HD;
        q[ob + i]        = __float2half_rn(x0 * cs - x1 * sn);
        q[ob + i + HALF] = __float2half_rn(x1 * cs + x0 * sn);
    } else {
        size_t base = (size_t)(b * SEQ + s) * HD;
        float x0 = g_kraw[base + i];
        float x1 = g_kraw[base + i + HALF];
        k[base + i]        = __float2half_rn(x0 * cs - x1 * sn);
        k[base + i + HALF] = __float2half_rn(x1 * cs + x0 * sn);
    }
}

// ---------------------------------------------------------------------------
// Causal softmax in place (vectorized) + single fp16 plane trimmed to the
// causal tile span that PV reads.
// ---------------------------------------------------------------------------
__global__ __launch_bounds__(256) void softmax_causal(
    float* __restrict__ attn, fp16* __restrict__ ahp)
{
    __shared__ float sm[SEQ];
    __shared__ float red[256];
    size_t row = blockIdx.x;
    int q = (int)(row % SEQ);
    float* r  = attn + row * SEQ;
    fp16*  rh = ahp  + row * SEQ;
    int n = q + 1;
    int n4 = n & ~3;
    int lim = ((q >> 7) + 1) << 7;
    int tid = threadIdx.x;

    float mx = -3.4e38f;
    for (int j = tid * 4; j < n4; j += 1024) {
        float4 v = *(const float4*)(r + j);
        *(float4*)(sm + j) = v;
        mx = fmaxf(mx, fmaxf(fmaxf(v.x, v.y), fmaxf(v.z, v.w)));
    }
    for (int j = n4 + tid; j < n; j += 256) { float v = r[j]; sm[j] = v; mx = fmaxf(mx, v); }
    red[tid] = mx; __syncthreads();
    for (int s = 128; s > 0; s >>= 1) { if (tid < s) red[tid] = fmaxf(red[tid], red[tid + s]); __syncthreads(); }
    mx = red[0];
    __syncthreads();

    float sum = 0.f;
    for (int j = tid; j < n; j += 256) { float e = expf(sm[j] - mx); sm[j] = e; sum += e; }
    red[tid] = sum; __syncthreads();
    for (int s = 128; s > 0; s >>= 1) { if (tid < s) red[tid] += red[tid + s]; __syncthreads(); }
    float inv = 1.f / red[0];

    for (int j = tid * 4; j < SEQ; j += 1024) {
        float4 o;
        o.x = (j + 0 < n) ? sm[j + 0] * inv : 0.f;
        o.y = (j + 1 < n) ? sm[j + 1] * inv : 0.f;
        o.z = (j + 2 < n) ? sm[j + 2] * inv : 0.f;
        o.w = (j + 3 < n) ? sm[j + 3] * inv : 0.f;
        *(float4*)(r + j) = o;
        if (j < lim) {
            uint2 hp;
            hp.x = pack2h(o.x, o.y);
            hp.y = pack2h(o.z, o.w);
            *(uint2*)(rh + j) = hp;
        }
    }
}

// ---------------------------------------------------------------------------
// Host launcher
// ---------------------------------------------------------------------------
extern "C" void kernel_launch(void* const* d_in, const int* in_sizes, int n_in,
                              void* d_out, int out_size)
{
    const float* hidden = (const float*)d_in[0];
    const float* Wq     = (const float*)d_in[1];
    const float* Wk     = (const float*)d_in[2];
    const float* Wv     = (const float*)d_in[3];
    const float* Wo     = (const float*)d_in[4];
    const int*   pos    = (const int*)d_in[6];

    float *qraw, *kraw, *attn_s;
    fp16 *hid, *wqkv, *wo, *q, *k, *v, *at, *ah;

    cudaGetSymbolAddress((void**)&qraw, g_qraw);
    cudaGetSymbolAddress((void**)&kraw, g_kraw);
    cudaGetSymbolAddress((void**)&attn_s, g_attn_s);
    cudaGetSymbolAddress((void**)&hid, g_hid);
    cudaGetSymbolAddress((void**)&wqkv, g_wqkv);
    cudaGetSymbolAddress((void**)&wo,  g_wo);
    cudaGetSymbolAddress((void**)&q,   g_q);
    cudaGetSymbolAddress((void**)&k,   g_k);
    cudaGetSymbolAddress((void**)&v,   g_v);
    cudaGetSymbolAddress((void**)&at,  g_at);
    cudaGetSymbolAddress((void**)&ah,  g_ah);

    float* out = (float*)d_out;
    const long long OUTE  = (long long)BDIM * SEQ * HID;
    const long long ATTNE = (long long)BDIM * NH * SEQ * SEQ;
    float* attn = ((long long)out_size >= OUTE + ATTNE) ? (out + OUTE) : attn_s;

    const int M = BDIM * SEQ;  // 4096

    const int AEL = BM * (BK + 8);            // 5120 elems
    const int BEL_NN = BK * (BN + 8);         // 4352 elems
    const int SM_NN1 = STAGES * (AEL + BEL_NN) * 2;        // 56832
    const int SM_NT1 = STAGES * (2 * AEL) * 2;             // 61440
    cudaFuncSetAttribute(gemm2p<false>, cudaFuncAttributeMaxDynamicSharedMemorySize, SM_NN1);
    cudaFuncSetAttribute(gemm2p<true>,  cudaFuncAttributeMaxDynamicSharedMemorySize, SM_NT1);

    // 1: all conversions
    conv_all<<<(CVTOT + 255) / 256, 256>>>(hidden, Wq, Wk, Wv, Wo, hid, wqkv, wo);

    // 2: merged QKV projection (single-pass, N=2560)
    gemm2p<false><<<dim3(2560/BN, M/BM, 1), 256, SM_NN1>>>(
        hid, nullptr, wqkv, qraw, kraw, v,
        HID, HID, 2560, HID, 1, 0,0,0,0,0,0, 0, 4);

    // 3: RoPE
    { int TOT = BDIM*SEQ*(NH+1)*HALF; rope_conv<<<(TOT+255)/256, 256>>>(pos, q, k); }

    // 4: scores = q @ k^T (single-pass), causal tile skip -> attn f32
    gemm2p<true><<<dim3(SEQ/BN, SEQ/BM, BDIM*NH), 256, SM_NT1>>>(
        q, nullptr, k, attn, nullptr, nullptr,
        HD, HD, HD, SEQ,
        NH,
        (long long)NH*SEQ*HD, (long long)SEQ*HD,
        (long long)SEQ*HD, 0,
        (long long)NH*SEQ*SEQ, (long long)SEQ*SEQ,
        1, 0);

    // 5: softmax (writes f32 attn output + single fp16 plane)
    softmax_causal<<<BDIM*NH*SEQ, 256>>>(attn, at);

    // 6: PV (single-pass) -> fp16 ah, causal K-limit
    gemm2p<false><<<dim3(HD/BN, SEQ/BM, BDIM*NH), 256, SM_NN1>>>(
        at, nullptr, v, nullptr, nullptr, ah,
        SEQ, SEQ, HD, NH*HD,
        NH,
        (long long)NH*SEQ*SEQ, (long long)SEQ*SEQ,
        (long long)SEQ*HD, 0,
        (long long)SEQ*NH*HD, (long long)HD,
        2, 3);

    // 7: out = ah @ Wo (single-pass)
    gemm2p<false><<<dim3(HID/BN, M/BM, 1), 256, SM_NN1>>>(
        ah, nullptr, wo, out, nullptr, nullptr,
        NH*HD, NH*HD, HID, HID, 1, 0,0,0,0,0,0, 0, 0);
}

// round 15
// speedup vs baseline: 6.5400x; 1.1231x over previous
#include <cuda_runtime.h>
#include <cuda_fp16.h>
#include <math.h>
#include <stdint.h>

#define BDIM 2
#define SEQ  2048
#define HID  2048
#define NH   8
#define HD   256
#define HALF 128

#define BM 128
#define BN 128
#define BK 32
#define STAGES 3

typedef __half fp16;

// ------------------------- static device scratch ---------------------------
__device__ __align__(16) float g_qraw[BDIM*SEQ*NH*HD];
__device__ __align__(16) float g_kraw[BDIM*SEQ*HD];
__device__ __align__(16) float g_attn_s[(size_t)BDIM*NH*SEQ*SEQ];
__device__ __align__(16) float g_rsum[BDIM*NH*SEQ];

__device__ __align__(16) fp16 g_hid[BDIM*SEQ*HID];
__device__ __align__(16) fp16 g_wqkv[HID*(NH*HD + 2*HD)];  // [2048, 2560] Wq|Wk|Wv
__device__ __align__(16) fp16 g_wo[NH*HD*HID];             // [2048, 2048]
__device__ __align__(16) fp16 g_q[BDIM*NH*SEQ*HD];
__device__ __align__(16) fp16 g_k[BDIM*SEQ*HD];
__device__ __align__(16) fp16 g_v[BDIM*SEQ*HD];
__device__ __align__(16) fp16 g_at[(size_t)BDIM*NH*SEQ*SEQ];   // unnormalized exp plane
__device__ __align__(16) fp16 g_ah[BDIM*SEQ*NH*HD];

// ------------------------------- helpers -----------------------------------
__device__ __forceinline__ uint32_t smem_u32(const void* p) {
    return (uint32_t)__cvta_generic_to_shared(p);
}
__device__ __forceinline__ void cp16a(void* dst, const void* src) {
    asm volatile("cp.async.cg.shared.global [%0], [%1], 16;\n"
                 :: "r"(smem_u32(dst)), "l"(src));
}
__device__ __forceinline__ void cp_commit() { asm volatile("cp.async.commit_group;\n"); }
template<int N> __device__ __forceinline__ void cp_wait() {
    asm volatile("cp.async.wait_group %0;\n" :: "n"(N));
}
__device__ __forceinline__ void ldm4(uint32_t r[4], uint32_t a) {
    asm volatile("ldmatrix.sync.aligned.m8n8.x4.shared.b16 {%0,%1,%2,%3}, [%4];\n"
                 : "=r"(r[0]), "=r"(r[1]), "=r"(r[2]), "=r"(r[3]) : "r"(a));
}
__device__ __forceinline__ void ldm4t(uint32_t r[4], uint32_t a) {
    asm volatile("ldmatrix.sync.aligned.m8n8.x4.trans.shared.b16 {%0,%1,%2,%3}, [%4];\n"
                 : "=r"(r[0]), "=r"(r[1]), "=r"(r[2]), "=r"(r[3]) : "r"(a));
}
__device__ __forceinline__ void mma_fp16(float c[4], const uint32_t a[4],
                                         uint32_t b0, uint32_t b1) {
    asm volatile(
        "mma.sync.aligned.m16n8k16.row.col.f32.f16.f16.f32 "
        "{%0,%1,%2,%3}, {%4,%5,%6,%7}, {%8,%9}, {%0,%1,%2,%3};\n"
        : "+f"(c[0]), "+f"(c[1]), "+f"(c[2]), "+f"(c[3])
        : "r"(a[0]), "r"(a[1]), "r"(a[2]), "r"(a[3]), "r"(b0), "r"(b1));
}
__device__ __forceinline__ uint32_t pack2h(float a, float b) {
    __half2 v = __floats2half2_rn(a, b);
    return *(uint32_t*)&v;
}
__device__ __forceinline__ uint2 f4h4(float4 v) {
    uint2 r; r.x = pack2h(v.x, v.y); r.y = pack2h(v.z, v.w); return r;
}

// ---------------------------------------------------------------------------
// fp16 GEMM (single or 2-pass A hi/lo; Al may be nullptr).
// NT=false: B [K,N] row-major.  NT=true: B [N,K] row-major (C = A·B^T).
// epi: 0 f32 C (ldc); 3 fp16 single Ch (ldc);
//      4 QKV triple: n0<2048 f32 C (ldc 2048); [2048,2304) f32 C2 (ldc 256);
//        >=2304 fp16 Ch (ldc 256);
//      5 fp16 Ch scaled by 1/rowsum[row]  (rowsum = RS + z*SEQ);
//      6 scores: e=exp(logit), causal mask, fp16 Ch + rowsum atomicAdd.
// cmode: 0 none; 1 (NT) causal tile-skip; 2 causal K-limit.
// 256 threads, warps 2(m) x 4(n), warp tile 64x32, 3-stage cp.async.
// ---------------------------------------------------------------------------
template<bool NT>
__global__ __launch_bounds__(256, 2) void gemm2p(
    const fp16* __restrict__ Ah, const fp16* __restrict__ Al,
    const fp16* __restrict__ Bs,
    float* __restrict__ C, float* __restrict__ C2, fp16* __restrict__ Ch,
    float* __restrict__ RS,
    int K, int lda, int ldb, int ldc,
    int zdiv, long long Ao, long long Ai, long long Bo, long long Bi,
    long long Co, long long Ci, int cmode, int epi)
{
    if (NT && cmode == 1 && blockIdx.x > blockIdx.y) return;

    constexpr int ASTR  = BK + 8;                  // 40
    constexpr int BROWS = NT ? BN : BK;
    constexpr int BSTR  = NT ? (BK + 8) : (BN + 8);
    constexpr int AELEM = BM * ASTR;               // 5120
    constexpr int BELEM = BROWS * BSTR;

    extern __shared__ fp16 smem[];
    const bool has_lo = (Al != nullptr);
    fp16* pAh = smem;
    fp16* pAl = pAh + STAGES * AELEM;
    fp16* pB  = has_lo ? (pAl + STAGES * AELEM) : pAl;

    int z = blockIdx.z;
    int zo = z / zdiv, zi = z - zo * zdiv;
    Ah += zo * Ao + zi * Ai;
    if (has_lo) Al += zo * Ao + zi * Ai;
    Bs += zo * Bo + zi * Bi;
    long long coff = zo * Co + zi * Ci;

    int m0 = blockIdx.y * BM, n0 = blockIdx.x * BN;
    int tid = threadIdx.x, lane = tid & 31, wid = tid >> 5;
    int wm = wid & 1, wn = wid >> 1;

    int kmax = (cmode == 2) ? min(K, m0 + BM) : K;
    int niter = kmax / BK;

    const int ar0 = tid >> 2,         ac0 = (tid & 3) * 8;
    const int ar1 = (tid + 256) >> 2, ac1 = ac0;
    const int br0 = tid >> 4,         bc0 = (tid & 15) * 8;
    const int br1 = (tid + 256) >> 4, bc1 = bc0;

    float c[4][4][4];
#pragma unroll
    for (int mt = 0; mt < 4; mt++)
#pragma unroll
        for (int nt = 0; nt < 4; nt++)
#pragma unroll
            for (int i = 0; i < 4; i++) c[mt][nt][i] = 0.f;

    auto load_stage = [&](int st, int k0) {
        fp16* ah = pAh + st * AELEM;  fp16* al = pAl + st * AELEM;
        fp16* bb = pB  + st * BELEM;
        cp16a(ah + ar0 * ASTR + ac0, Ah + (size_t)(m0 + ar0) * lda + k0 + ac0);
        cp16a(ah + ar1 * ASTR + ac1, Ah + (size_t)(m0 + ar1) * lda + k0 + ac1);
        if (has_lo) {
            cp16a(al + ar0 * ASTR + ac0, Al + (size_t)(m0 + ar0) * lda + k0 + ac0);
            cp16a(al + ar1 * ASTR + ac1, Al + (size_t)(m0 + ar1) * lda + k0 + ac1);
        }
        if (NT) {
            cp16a(bb + ar0 * BSTR + ac0, Bs + (size_t)(n0 + ar0) * ldb + k0 + ac0);
            cp16a(bb + ar1 * BSTR + ac1, Bs + (size_t)(n0 + ar1) * ldb + k0 + ac1);
        } else {
            cp16a(bb + br0 * BSTR + bc0, Bs + (size_t)(k0 + br0) * ldb + n0 + bc0);
            cp16a(bb + br1 * BSTR + bc1, Bs + (size_t)(k0 + br1) * ldb + n0 + bc1);
        }
    };

#pragma unroll
    for (int s = 0; s < STAGES - 1; s++) {
        if (s < niter) load_stage(s, s * BK);
        cp_commit();
    }

    for (int it = 0; it < niter; it++) {
        cp_wait<STAGES - 2>();
        __syncthreads();

        int nk = it + STAGES - 1;
        if (nk < niter) load_stage(nk % STAGES, nk * BK);
        cp_commit();

        int st = it % STAGES;
        const fp16* ah = pAh + st * AELEM;
        const fp16* al = pAl + st * AELEM;
        const fp16* bb = pB  + st * BELEM;

#pragma unroll
        for (int ks = 0; ks < BK; ks += 16) {
            uint32_t fa[4][4], fb[8];
#pragma unroll
            for (int mt = 0; mt < 4; mt++) {
                int row = wm * 64 + mt * 16 + (lane & 15);
                int col = ks + ((lane >> 4) << 3);
                ldm4(fa[mt], smem_u32(ah + row * ASTR + col));
            }
#pragma unroll
            for (int p = 0; p < 2; p++) {
                if (NT) {
                    int row = wn * 32 + p * 16 + (lane & 7) + ((lane >> 4) << 3);
                    int col = ks + (lane & 8);
                    ldm4(&fb[4 * p], smem_u32(bb + row * BSTR + col));
                } else {
                    int row = ks + (lane & 15);
                    int col = wn * 32 + p * 16 + ((lane >> 4) << 3);
                    ldm4t(&fb[4 * p], smem_u32(bb + row * BSTR + col));
                }
            }
#pragma unroll
            for (int mt = 0; mt < 4; mt++)
#pragma unroll
                for (int nt = 0; nt < 4; nt++)
                    mma_fp16(c[mt][nt], fa[mt], fb[2*nt], fb[2*nt+1]);
            if (has_lo) {
#pragma unroll
                for (int mt = 0; mt < 4; mt++) {
                    int row = wm * 64 + mt * 16 + (lane & 15);
                    int col = ks + ((lane >> 4) << 3);
                    ldm4(fa[mt], smem_u32(al + row * ASTR + col));
                }
#pragma unroll
                for (int mt = 0; mt < 4; mt++)
#pragma unroll
                    for (int nt = 0; nt < 4; nt++)
                        mma_fp16(c[mt][nt], fa[mt], fb[2*nt], fb[2*nt+1]);
            }
        }
        __syncthreads();
    }

    // ============================= epilogues =============================
    if (epi == 6) {
        // scores: e = exp(logit), causal mask, fp16 plane + row sums
        cp_wait<0>();
        __syncthreads();
        float* rs = (float*)smem;                   // overlay [4][128]
        float* rsum = RS + (size_t)z * SEQ;
#pragma unroll
        for (int mt = 0; mt < 4; mt++) {
            int lrow0 = wm * 64 + mt * 16 + (lane >> 2);
            int grow0 = m0 + lrow0;
            float ps0 = 0.f, ps1 = 0.f;
#pragma unroll
            for (int nt = 0; nt < 4; nt++) {
                int gcol = n0 + wn * 32 + nt * 8 + (lane & 3) * 2;
                float e0 = (gcol     <= grow0)     ? __expf(c[mt][nt][0]) : 0.f;
                float e1 = (gcol + 1 <= grow0)     ? __expf(c[mt][nt][1]) : 0.f;
                float e2 = (gcol     <= grow0 + 8) ? __expf(c[mt][nt][2]) : 0.f;
                float e3 = (gcol + 1 <= grow0 + 8) ? __expf(c[mt][nt][3]) : 0.f;
                size_t o0 = (size_t)coff + (size_t)grow0 * ldc + gcol;
                *(uint32_t*)(Ch + o0)                    = pack2h(e0, e1);
                *(uint32_t*)(Ch + o0 + 8 * (size_t)ldc) = pack2h(e2, e3);
                ps0 += e0 + e1; ps1 += e2 + e3;
            }
            ps0 += __shfl_xor_sync(0xffffffffu, ps0, 1);
            ps0 += __shfl_xor_sync(0xffffffffu, ps0, 2);
            ps1 += __shfl_xor_sync(0xffffffffu, ps1, 1);
            ps1 += __shfl_xor_sync(0xffffffffu, ps1, 2);
            if ((lane & 3) == 0) {
                rs[wn * 128 + lrow0]     = ps0;
                rs[wn * 128 + lrow0 + 8] = ps1;
            }
        }
        __syncthreads();
        if (tid < 128) {
            float s = rs[tid] + rs[128 + tid] + rs[256 + tid] + rs[384 + tid];
            atomicAdd(&rsum[m0 + tid], s);
        }
        return;
    }
    if (epi == 5) {
        // PV: normalize by rowsum, fp16 out
        const float* rsum = RS + (size_t)z * SEQ;
#pragma unroll
        for (int mt = 0; mt < 4; mt++) {
            int row = m0 + wm * 64 + mt * 16 + (lane >> 2);
            float inv0 = 1.f / rsum[row];
            float inv1 = 1.f / rsum[row + 8];
#pragma unroll
            for (int nt = 0; nt < 4; nt++) {
                int col = n0 + wn * 32 + nt * 8 + (lane & 3) * 2;
                size_t o0 = (size_t)coff + (size_t)row * ldc + col;
                *(uint32_t*)(Ch + o0) = pack2h(c[mt][nt][0] * inv0, c[mt][nt][1] * inv0);
                *(uint32_t*)(Ch + o0 + 8 * (size_t)ldc) =
                    pack2h(c[mt][nt][2] * inv1, c[mt][nt][3] * inv1);
            }
        }
        return;
    }

    // generic modes 0 / 3 / 4
    int mode = epi;
    int nbase = n0;
    int ld = ldc;
    float* Cf = C;
    if (epi == 4) {
        if (n0 < 2048)      { mode = 0; ld = 2048; }
        else if (n0 < 2304) { mode = 0; Cf = C2; ld = 256; nbase = n0 - 2048; }
        else                { mode = 3; ld = 256; nbase = n0 - 2304; }
    }
#pragma unroll
    for (int mt = 0; mt < 4; mt++)
#pragma unroll
        for (int nt = 0; nt < 4; nt++) {
            int row = m0 + wm * 64 + mt * 16 + (lane >> 2);
            int col = nbase + wn * 32 + nt * 8 + (lane & 3) * 2;
            size_t o0 = (size_t)coff + (size_t)row * ld + col;
            size_t o1 = (size_t)coff + (size_t)(row + 8) * ld + col;
            float f0 = c[mt][nt][0], f1 = c[mt][nt][1];
            float f2 = c[mt][nt][2], f3 = c[mt][nt][3];
            if (mode == 0) {
                *(float2*)(Cf + o0) = make_float2(f0, f1);
                *(float2*)(Cf + o1) = make_float2(f2, f3);
            } else {  // mode 3
                *(uint32_t*)(Ch + o0) = pack2h(f0, f1);
                *(uint32_t*)(Ch + o1) = pack2h(f2, f3);
            }
        }
}

// ---------------------------------------------------------------------------
// Vectorized (x4) input conversions + rowsum zeroing, one kernel.
// ---------------------------------------------------------------------------
#define CVN0 (BDIM*SEQ*HID)
#define CVN1 (HID*NH*HD)
#define CVN2 (HID*HD)
#define CV4_0 (CVN0/4)
#define CV4_1 (CVN1/4)
#define CV4_2 (CVN2/4)
#define RSN4  (BDIM*NH*SEQ/4)
#define CV4TOT (CV4_0 + CV4_1 + 2*CV4_2 + CV4_1 + RSN4)

__global__ void conv_all(const float* __restrict__ hidden,
                         const float* __restrict__ Wq, const float* __restrict__ Wk,
                         const float* __restrict__ Wv, const float* __restrict__ Wo,
                         fp16* __restrict__ hid, fp16* __restrict__ wqkv,
                         fp16* __restrict__ wo, float* __restrict__ rsum)
{
    int t = blockIdx.x * 256 + threadIdx.x;
    if (t < CV4_0) { ((uint2*)hid)[t] = f4h4(((const float4*)hidden)[t]); return; }
    t -= CV4_0;
    if (t < CV4_1) {
        int i4 = t * 4, r = i4 >> 11, c0 = i4 & 2047;
        *(uint2*)(wqkv + (size_t)r * 2560 + c0) = f4h4(((const float4*)Wq)[t]);
        return;
    }
    t -= CV4_1;
    if (t < CV4_2) {
        int i4 = t * 4, r = i4 >> 8, c0 = i4 & 255;
        *(uint2*)(wqkv + (size_t)r * 2560 + 2048 + c0) = f4h4(((const float4*)Wk)[t]);
        return;
    }
    t -= CV4_2;
    if (t < CV4_2) {
        int i4 = t * 4, r = i4 >> 8, c0 = i4 & 255;
        *(uint2*)(wqkv + (size_t)r * 2560 + 2304 + c0) = f4h4(((const float4*)Wv)[t]);
        return;
    }
    t -= CV4_2;
    if (t < CV4_1) { ((uint2*)wo)[t] = f4h4(((const float4*)Wo)[t]); return; }
    t -= CV4_1;
    if (t < RSN4) ((float4*)rsum)[t] = make_float4(0.f, 0.f, 0.f, 0.f);
}

// ---------------------------------------------------------------------------
// RoPE: qraw [B,S,H,D] -> q fp16 [B,H,S,D] (scaled 1/16); kraw -> k fp16
// ---------------------------------------------------------------------------
__global__ void rope_conv(const int* __restrict__ pos,
                          fp16* __restrict__ q, fp16* __restrict__ k)
{
    int t = blockIdx.x * 256 + threadIdx.x;
    const int TOT = BDIM * SEQ * (NH + 1) * HALF;
    if (t >= TOT) return;
    int i = t & (HALF - 1);
    int rest = t >> 7;
    int hh = rest % (NH + 1); rest /= (NH + 1);
    int s = rest % SEQ;
    int b = rest / SEQ;

    float p = (float)pos[b * SEQ + s];
    float freq = powf(10000.f, -(float)(2 * i) / (float)HD);
    float ang = p * freq;
    float sn, cs;
    sincosf(ang, &sn, &cs);

    if (hh < NH) {
        size_t base = ((size_t)(b * SEQ + s) * NH + hh) * HD;
        float x0 = g_qraw[base + i] * 0.0625f;
        float x1 = g_qraw[base + i + HALF] * 0.0625f;
        size_t ob = ((size_t)(b * NH + hh) * SEQ + s) * HD;
        q[ob + i]        = __float2half_rn(x0 * cs - x1 * sn);
        q[ob + i + HALF] = __float2half_rn(x1 * cs + x0 * sn);
    } else {
        size_t base = (size_t)(b * SEQ + s) * HD;
        float x0 = g_kraw[base + i];
        float x1 = g_kraw[base + i + HALF];
        k[base + i]        = __float2half_rn(x0 * cs - x1 * sn);
        k[base + i + HALF] = __float2half_rn(x1 * cs + x0 * sn);
    }
}

// ---------------------------------------------------------------------------
// Normalize: attn[row][j] = e[j] / rowsum[row] (f32 output), zero tail.
// One block per row; reads only the causal tile span.
// ---------------------------------------------------------------------------
__global__ __launch_bounds__(256) void normalize_attn(
    const fp16* __restrict__ at, const float* __restrict__ rsum,
    float* __restrict__ attn)
{
    int row = blockIdx.x;
    int q = row & (SEQ - 1);
    float inv = 1.f / rsum[row];
    const fp16* re = at + (size_t)row * SEQ;
    float* ro = attn + (size_t)row * SEQ;
    int lim = ((q >> 7) + 1) << 7;
    int tid = threadIdx.x;

    for (int j = tid * 4; j < lim; j += 1024) {
        uint2 hv = *(const uint2*)(re + j);
        float2 a = __half22float2(*(__half2*)&hv.x);
        float2 b = __half22float2(*(__half2*)&hv.y);
        *(float4*)(ro + j) = make_float4(a.x * inv, a.y * inv, b.x * inv, b.y * inv);
    }
    for (int j = lim + tid * 4; j < SEQ; j += 1024)
        *(float4*)(ro + j) = make_float4(0.f, 0.f, 0.f, 0.f);
}

// ---------------------------------------------------------------------------
// Host launcher
// ---------------------------------------------------------------------------
extern "C" void kernel_launch(void* const* d_in, const int* in_sizes, int n_in,
                              void* d_out, int out_size)
{
    const float* hidden = (const float*)d_in[0];
    const float* Wq     = (const float*)d_in[1];
    const float* Wk     = (const float*)d_in[2];
    const float* Wv     = (const float*)d_in[3];
    const float* Wo     = (const float*)d_in[4];
    const int*   pos    = (const int*)d_in[6];

    float *qraw, *kraw, *attn_s, *rsum;
    fp16 *hid, *wqkv, *wo, *q, *k, *v, *at, *ah;

    cudaGetSymbolAddress((void**)&qraw, g_qraw);
    cudaGetSymbolAddress((void**)&kraw, g_kraw);
    cudaGetSymbolAddress((void**)&attn_s, g_attn_s);
    cudaGetSymbolAddress((void**)&rsum, g_rsum);
    cudaGetSymbolAddress((void**)&hid, g_hid);
    cudaGetSymbolAddress((void**)&wqkv, g_wqkv);
    cudaGetSymbolAddress((void**)&wo,  g_wo);
    cudaGetSymbolAddress((void**)&q,   g_q);
    cudaGetSymbolAddress((void**)&k,   g_k);
    cudaGetSymbolAddress((void**)&v,   g_v);
    cudaGetSymbolAddress((void**)&at,  g_at);
    cudaGetSymbolAddress((void**)&ah,  g_ah);

    float* out = (float*)d_out;
    const long long OUTE  = (long long)BDIM * SEQ * HID;
    const long long ATTNE = (long long)BDIM * NH * SEQ * SEQ;
    float* attn = ((long long)out_size >= OUTE + ATTNE) ? (out + OUTE) : attn_s;

    const int M = BDIM * SEQ;  // 4096

    const int AEL = BM * (BK + 8);            // 5120 elems
    const int BEL_NN = BK * (BN + 8);         // 4352 elems
    const int SM_NN1 = STAGES * (AEL + BEL_NN) * 2;        // 56832
    const int SM_NT1 = STAGES * (2 * AEL) * 2;             // 61440
    cudaFuncSetAttribute(gemm2p<false>, cudaFuncAttributeMaxDynamicSharedMemorySize, SM_NN1);
    cudaFuncSetAttribute(gemm2p<true>,  cudaFuncAttributeMaxDynamicSharedMemorySize, SM_NT1);

    // 1: conversions + rowsum zeroing
    conv_all<<<(CV4TOT + 255) / 256, 256>>>(hidden, Wq, Wk, Wv, Wo, hid, wqkv, wo, rsum);

    // 2: merged QKV projection (single-pass, N=2560)
    gemm2p<false><<<dim3(2560/BN, M/BM, 1), 256, SM_NN1>>>(
        hid, nullptr, wqkv, qraw, kraw, v, nullptr,
        HID, HID, 2560, HID, 1, 0,0,0,0,0,0, 0, 4);

    // 3: RoPE
    { int TOT = BDIM*SEQ*(NH+1)*HALF; rope_conv<<<(TOT+255)/256, 256>>>(pos, q, k); }

    // 4: scores = q @ k^T, fused exp + rowsum -> fp16 e-plane (no f32 logits)
    gemm2p<true><<<dim3(SEQ/BN, SEQ/BM, BDIM*NH), 256, SM_NT1>>>(
        q, nullptr, k, nullptr, nullptr, at, rsum,
        HD, HD, HD, SEQ,
        NH,
        (long long)NH*SEQ*HD, (long long)SEQ*HD,
        (long long)SEQ*HD, 0,
        (long long)NH*SEQ*SEQ, (long long)SEQ*SEQ,
        1, 6);

    // 5: normalize e-plane into the f32 attn output
    normalize_attn<<<BDIM*NH*SEQ, 256>>>(at, rsum, attn);

    // 6: PV (single-pass on unnormalized e), epilogue divides by rowsum
    gemm2p<false><<<dim3(HD/BN, SEQ/BM, BDIM*NH), 256, SM_NN1>>>(
        at, nullptr, v, nullptr, nullptr, ah, rsum,
        SEQ, SEQ, HD, NH*HD,
        NH,
        (long long)NH*SEQ*SEQ, (long long)SEQ*SEQ,
        (long long)SEQ*HD, 0,
        (long long)SEQ*NH*HD, (long long)HD,
        2, 5);

    // 7: out = ah @ Wo (single-pass)
    gemm2p<false><<<dim3(HID/BN, M/BM, 1), 256, SM_NN1>>>(
        ah, nullptr, wo, out, nullptr, nullptr, nullptr,
        NH*HD, NH*HD, HID, HID, 1, 0,0,0,0,0,0, 0, 0);
}

// round 16
// speedup vs baseline: 6.9132x; 1.0571x over previous
#include <cuda_runtime.h>
#include <cuda_fp16.h>
#include <math.h>
#include <stdint.h>

#define BDIM 2
#define SEQ  2048
#define HID  2048
#define NH   8
#define HD   256
#define HALF 128

#define BM 128
#define BN 128
#define BK 32
#define STAGES 3

typedef __half fp16;

// ------------------------- static device scratch ---------------------------
__device__ __align__(16) float g_qraw[BDIM*SEQ*NH*HD];
__device__ __align__(16) float g_kraw[BDIM*SEQ*HD];
__device__ __align__(16) float g_attn_s[(size_t)BDIM*NH*SEQ*SEQ];
__device__ __align__(16) float g_rsum[BDIM*NH*SEQ];

__device__ __align__(16) fp16 g_hid[BDIM*SEQ*HID];
__device__ __align__(16) fp16 g_wqkv[HID*(NH*HD + 2*HD)];  // [2048, 2560] Wq|Wk|Wv
__device__ __align__(16) fp16 g_wo[NH*HD*HID];             // [2048, 2048]
__device__ __align__(16) fp16 g_q[BDIM*NH*SEQ*HD];
__device__ __align__(16) fp16 g_k[BDIM*SEQ*HD];
__device__ __align__(16) fp16 g_v[BDIM*SEQ*HD];
__device__ __align__(16) fp16 g_at[(size_t)BDIM*NH*SEQ*SEQ];   // unnormalized exp plane
__device__ __align__(16) fp16 g_ah[BDIM*SEQ*NH*HD];

// ------------------------------- helpers -----------------------------------
__device__ __forceinline__ uint32_t smem_u32(const void* p) {
    return (uint32_t)__cvta_generic_to_shared(p);
}
__device__ __forceinline__ void cp16a(void* dst, const void* src) {
    asm volatile("cp.async.cg.shared.global [%0], [%1], 16;\n"
                 :: "r"(smem_u32(dst)), "l"(src));
}
__device__ __forceinline__ void cp_commit() { asm volatile("cp.async.commit_group;\n"); }
template<int N> __device__ __forceinline__ void cp_wait() {
    asm volatile("cp.async.wait_group %0;\n" :: "n"(N));
}
__device__ __forceinline__ void ldm4(uint32_t r[4], uint32_t a) {
    asm volatile("ldmatrix.sync.aligned.m8n8.x4.shared.b16 {%0,%1,%2,%3}, [%4];\n"
                 : "=r"(r[0]), "=r"(r[1]), "=r"(r[2]), "=r"(r[3]) : "r"(a));
}
__device__ __forceinline__ void ldm4t(uint32_t r[4], uint32_t a) {
    asm volatile("ldmatrix.sync.aligned.m8n8.x4.trans.shared.b16 {%0,%1,%2,%3}, [%4];\n"
                 : "=r"(r[0]), "=r"(r[1]), "=r"(r[2]), "=r"(r[3]) : "r"(a));
}
__device__ __forceinline__ void mma_fp16(float c[4], const uint32_t a[4],
                                         uint32_t b0, uint32_t b1) {
    asm volatile(
        "mma.sync.aligned.m16n8k16.row.col.f32.f16.f16.f32 "
        "{%0,%1,%2,%3}, {%4,%5,%6,%7}, {%8,%9}, {%0,%1,%2,%3};\n"
        : "+f"(c[0]), "+f"(c[1]), "+f"(c[2]), "+f"(c[3])
        : "r"(a[0]), "r"(a[1]), "r"(a[2]), "r"(a[3]), "r"(b0), "r"(b1));
}
__device__ __forceinline__ uint32_t pack2h(float a, float b) {
    __half2 v = __floats2half2_rn(a, b);
    return *(uint32_t*)&v;
}
__device__ __forceinline__ uint2 f4h4(float4 v) {
    uint2 r; r.x = pack2h(v.x, v.y); r.y = pack2h(v.z, v.w); return r;
}

// ---------------------------------------------------------------------------
// fp16 GEMM (single or 2-pass A hi/lo; Al may be nullptr).
// NT=false: B [K,N] row-major.  NT=true: B [N,K] row-major (C = A·B^T).
// epi: 0 f32 C (ldc); 3 fp16 single Ch (ldc);
//      4 QKV triple: n0<2048 f32 C (ldc 2048); [2048,2304) f32 C2 (ldc 256);
//        >=2304 fp16 Ch (ldc 256);
//      5 fp16 Ch scaled by 1/rowsum[row]  (rowsum = RS + z*SEQ);
//      6 scores: e=exp(logit), causal mask, fp16 Ch + rowsum atomicAdd.
// cmode: 0 none; 1 (NT) causal tile-skip; 2 causal K-limit.
// 256 threads, warps 2(m) x 4(n), warp tile 64x32, 3-stage cp.async.
// Mainloop software-pipelines register fragments: both ks B-fragments are
// prefetched up front; A-fragments of ks1 overlap ks0's MMAs.
// ---------------------------------------------------------------------------
template<bool NT>
__global__ __launch_bounds__(256, 2) void gemm2p(
    const fp16* __restrict__ Ah, const fp16* __restrict__ Al,
    const fp16* __restrict__ Bs,
    float* __restrict__ C, float* __restrict__ C2, fp16* __restrict__ Ch,
    float* __restrict__ RS,
    int K, int lda, int ldb, int ldc,
    int zdiv, long long Ao, long long Ai, long long Bo, long long Bi,
    long long Co, long long Ci, int cmode, int epi)
{
    if (NT && cmode == 1 && blockIdx.x > blockIdx.y) return;

    constexpr int ASTR  = BK + 8;                  // 40
    constexpr int BROWS = NT ? BN : BK;
    constexpr int BSTR  = NT ? (BK + 8) : (BN + 8);
    constexpr int AELEM = BM * ASTR;               // 5120
    constexpr int BELEM = BROWS * BSTR;

    extern __shared__ fp16 smem[];
    const bool has_lo = (Al != nullptr);
    fp16* pAh = smem;
    fp16* pAl = pAh + STAGES * AELEM;
    fp16* pB  = has_lo ? (pAl + STAGES * AELEM) : pAl;

    int z = blockIdx.z;
    int zo = z / zdiv, zi = z - zo * zdiv;
    Ah += zo * Ao + zi * Ai;
    if (has_lo) Al += zo * Ao + zi * Ai;
    Bs += zo * Bo + zi * Bi;
    long long coff = zo * Co + zi * Ci;

    int m0 = blockIdx.y * BM, n0 = blockIdx.x * BN;
    int tid = threadIdx.x, lane = tid & 31, wid = tid >> 5;
    int wm = wid & 1, wn = wid >> 1;

    int kmax = (cmode == 2) ? min(K, m0 + BM) : K;
    int niter = kmax / BK;

    const int ar0 = tid >> 2,         ac0 = (tid & 3) * 8;
    const int ar1 = (tid + 256) >> 2, ac1 = ac0;
    const int br0 = tid >> 4,         bc0 = (tid & 15) * 8;
    const int br1 = (tid + 256) >> 4, bc1 = bc0;

    float c[4][4][4];
#pragma unroll
    for (int mt = 0; mt < 4; mt++)
#pragma unroll
        for (int nt = 0; nt < 4; nt++)
#pragma unroll
            for (int i = 0; i < 4; i++) c[mt][nt][i] = 0.f;

    auto load_stage = [&](int st, int k0) {
        fp16* ah = pAh + st * AELEM;  fp16* al = pAl + st * AELEM;
        fp16* bb = pB  + st * BELEM;
        cp16a(ah + ar0 * ASTR + ac0, Ah + (size_t)(m0 + ar0) * lda + k0 + ac0);
        cp16a(ah + ar1 * ASTR + ac1, Ah + (size_t)(m0 + ar1) * lda + k0 + ac1);
        if (has_lo) {
            cp16a(al + ar0 * ASTR + ac0, Al + (size_t)(m0 + ar0) * lda + k0 + ac0);
            cp16a(al + ar1 * ASTR + ac1, Al + (size_t)(m0 + ar1) * lda + k0 + ac1);
        }
        if (NT) {
            cp16a(bb + ar0 * BSTR + ac0, Bs + (size_t)(n0 + ar0) * ldb + k0 + ac0);
            cp16a(bb + ar1 * BSTR + ac1, Bs + (size_t)(n0 + ar1) * ldb + k0 + ac1);
        } else {
            cp16a(bb + br0 * BSTR + bc0, Bs + (size_t)(k0 + br0) * ldb + n0 + bc0);
            cp16a(bb + br1 * BSTR + bc1, Bs + (size_t)(k0 + br1) * ldb + n0 + bc1);
        }
    };

    // B-fragment loader for k-step base `ks`
    auto load_fb = [&](uint32_t* fb, const fp16* bb, int ks) {
#pragma unroll
        for (int p = 0; p < 2; p++) {
            if (NT) {
                int row = wn * 32 + p * 16 + (lane & 7) + ((lane >> 4) << 3);
                int col = ks + (lane & 8);
                ldm4(&fb[4 * p], smem_u32(bb + row * BSTR + col));
            } else {
                int row = ks + (lane & 15);
                int col = wn * 32 + p * 16 + ((lane >> 4) << 3);
                ldm4t(&fb[4 * p], smem_u32(bb + row * BSTR + col));
            }
        }
    };
    // A-fragment loader (one plane) for k-step `ks`
    auto load_fa = [&](uint32_t fa[4][4], const fp16* ap, int ks) {
#pragma unroll
        for (int mt = 0; mt < 4; mt++) {
            int row = wm * 64 + mt * 16 + (lane & 15);
            int col = ks + ((lane >> 4) << 3);
            ldm4(fa[mt], smem_u32(ap + row * ASTR + col));
        }
    };
    auto do_mma = [&](uint32_t fa[4][4], const uint32_t* fb) {
#pragma unroll
        for (int mt = 0; mt < 4; mt++)
#pragma unroll
            for (int nt = 0; nt < 4; nt++)
                mma_fp16(c[mt][nt], fa[mt], fb[2*nt], fb[2*nt+1]);
    };

#pragma unroll
    for (int s = 0; s < STAGES - 1; s++) {
        if (s < niter) load_stage(s, s * BK);
        cp_commit();
    }

    for (int it = 0; it < niter; it++) {
        cp_wait<STAGES - 2>();
        __syncthreads();

        int nk = it + STAGES - 1;
        if (nk < niter) load_stage(nk % STAGES, nk * BK);
        cp_commit();

        int st = it % STAGES;
        const fp16* ah = pAh + st * AELEM;
        const fp16* al = pAl + st * AELEM;
        const fp16* bb = pB  + st * BELEM;

        // ---- software-pipelined fragment schedule over the 2 k-steps ----
        uint32_t fb0[8], fb1[8], fa[4][4];
        load_fb(fb0, bb, 0);            // B ks0
        load_fa(fa, ah, 0);             // A ks0
        load_fb(fb1, bb, 16);           // B ks1 (overlaps ks0 MMAs below)
        do_mma(fa, fb0);                // MMA ks0
        load_fa(fa, ah, 16);            // A ks1 (overlaps tail of ks0 MMAs)
        do_mma(fa, fb1);                // MMA ks1
        if (has_lo) {
            load_fa(fa, al, 0);
            do_mma(fa, fb0);
            load_fa(fa, al, 16);
            do_mma(fa, fb1);
        }
        __syncthreads();
    }

    // ============================= epilogues =============================
    if (epi == 6) {
        // scores: e = exp(logit), causal mask, fp16 plane + row sums
        cp_wait<0>();
        __syncthreads();
        float* rs = (float*)smem;                   // overlay [4][128]
        float* rsum = RS + (size_t)z * SEQ;
#pragma unroll
        for (int mt = 0; mt < 4; mt++) {
            int lrow0 = wm * 64 + mt * 16 + (lane >> 2);
            int grow0 = m0 + lrow0;
            float ps0 = 0.f, ps1 = 0.f;
#pragma unroll
            for (int nt = 0; nt < 4; nt++) {
                int gcol = n0 + wn * 32 + nt * 8 + (lane & 3) * 2;
                float e0 = (gcol     <= grow0)     ? __expf(c[mt][nt][0]) : 0.f;
                float e1 = (gcol + 1 <= grow0)     ? __expf(c[mt][nt][1]) : 0.f;
                float e2 = (gcol     <= grow0 + 8) ? __expf(c[mt][nt][2]) : 0.f;
                float e3 = (gcol + 1 <= grow0 + 8) ? __expf(c[mt][nt][3]) : 0.f;
                size_t o0 = (size_t)coff + (size_t)grow0 * ldc + gcol;
                *(uint32_t*)(Ch + o0)                    = pack2h(e0, e1);
                *(uint32_t*)(Ch + o0 + 8 * (size_t)ldc) = pack2h(e2, e3);
                ps0 += e0 + e1; ps1 += e2 + e3;
            }
            ps0 += __shfl_xor_sync(0xffffffffu, ps0, 1);
            ps0 += __shfl_xor_sync(0xffffffffu, ps0, 2);
            ps1 += __shfl_xor_sync(0xffffffffu, ps1, 1);
            ps1 += __shfl_xor_sync(0xffffffffu, ps1, 2);
            if ((lane & 3) == 0) {
                rs[wn * 128 + lrow0]     = ps0;
                rs[wn * 128 + lrow0 + 8] = ps1;
            }
        }
        __syncthreads();
        if (tid < 128) {
            float s = rs[tid] + rs[128 + tid] + rs[256 + tid] + rs[384 + tid];
            atomicAdd(&rsum[m0 + tid], s);
        }
        return;
    }
    if (epi == 5) {
        // PV: normalize by rowsum, fp16 out
        const float* rsum = RS + (size_t)z * SEQ;
#pragma unroll
        for (int mt = 0; mt < 4; mt++) {
            int row = m0 + wm * 64 + mt * 16 + (lane >> 2);
            float inv0 = 1.f / rsum[row];
            float inv1 = 1.f / rsum[row + 8];
#pragma unroll
            for (int nt = 0; nt < 4; nt++) {
                int col = n0 + wn * 32 + nt * 8 + (lane & 3) * 2;
                size_t o0 = (size_t)coff + (size_t)row * ldc + col;
                *(uint32_t*)(Ch + o0) = pack2h(c[mt][nt][0] * inv0, c[mt][nt][1] * inv0);
                *(uint32_t*)(Ch + o0 + 8 * (size_t)ldc) =
                    pack2h(c[mt][nt][2] * inv1, c[mt][nt][3] * inv1);
            }
        }
        return;
    }

    // generic modes 0 / 3 / 4
    int mode = epi;
    int nbase = n0;
    int ld = ldc;
    float* Cf = C;
    if (epi == 4) {
        if (n0 < 2048)      { mode = 0; ld = 2048; }
        else if (n0 < 2304) { mode = 0; Cf = C2; ld = 256; nbase = n0 - 2048; }
        else                { mode = 3; ld = 256; nbase = n0 - 2304; }
    }
#pragma unroll
    for (int mt = 0; mt < 4; mt++)
#pragma unroll
        for (int nt = 0; nt < 4; nt++) {
            int row = m0 + wm * 64 + mt * 16 + (lane >> 2);
            int col = nbase + wn * 32 + nt * 8 + (lane & 3) * 2;
            size_t o0 = (size_t)coff + (size_t)row * ld + col;
            size_t o1 = (size_t)coff + (size_t)(row + 8) * ld + col;
            float f0 = c[mt][nt][0], f1 = c[mt][nt][1];
            float f2 = c[mt][nt][2], f3 = c[mt][nt][3];
            if (mode == 0) {
                *(float2*)(Cf + o0) = make_float2(f0, f1);
                *(float2*)(Cf + o1) = make_float2(f2, f3);
            } else {  // mode 3
                *(uint32_t*)(Ch + o0) = pack2h(f0, f1);
                *(uint32_t*)(Ch + o1) = pack2h(f2, f3);
            }
        }
}

// ---------------------------------------------------------------------------
// Vectorized (x4) input conversions + rowsum zeroing, one kernel.
// ---------------------------------------------------------------------------
#define CVN0 (BDIM*SEQ*HID)
#define CVN1 (HID*NH*HD)
#define CVN2 (HID*HD)
#define CV4_0 (CVN0/4)
#define CV4_1 (CVN1/4)
#define CV4_2 (CVN2/4)
#define RSN4  (BDIM*NH*SEQ/4)
#define CV4TOT (CV4_0 + CV4_1 + 2*CV4_2 + CV4_1 + RSN4)

__global__ void conv_all(const float* __restrict__ hidden,
                         const float* __restrict__ Wq, const float* __restrict__ Wk,
                         const float* __restrict__ Wv, const float* __restrict__ Wo,
                         fp16* __restrict__ hid, fp16* __restrict__ wqkv,
                         fp16* __restrict__ wo, float* __restrict__ rsum)
{
    int t = blockIdx.x * 256 + threadIdx.x;
    if (t < CV4_0) { ((uint2*)hid)[t] = f4h4(((const float4*)hidden)[t]); return; }
    t -= CV4_0;
    if (t < CV4_1) {
        int i4 = t * 4, r = i4 >> 11, c0 = i4 & 2047;
        *(uint2*)(wqkv + (size_t)r * 2560 + c0) = f4h4(((const float4*)Wq)[t]);
        return;
    }
    t -= CV4_1;
    if (t < CV4_2) {
        int i4 = t * 4, r = i4 >> 8, c0 = i4 & 255;
        *(uint2*)(wqkv + (size_t)r * 2560 + 2048 + c0) = f4h4(((const float4*)Wk)[t]);
        return;
    }
    t -= CV4_2;
    if (t < CV4_2) {
        int i4 = t * 4, r = i4 >> 8, c0 = i4 & 255;
        *(uint2*)(wqkv + (size_t)r * 2560 + 2304 + c0) = f4h4(((const float4*)Wv)[t]);
        return;
    }
    t -= CV4_2;
    if (t < CV4_1) { ((uint2*)wo)[t] = f4h4(((const float4*)Wo)[t]); return; }
    t -= CV4_1;
    if (t < RSN4) ((float4*)rsum)[t] = make_float4(0.f, 0.f, 0.f, 0.f);
}

// ---------------------------------------------------------------------------
// RoPE: qraw [B,S,H,D] -> q fp16 [B,H,S,D] (scaled 1/16); kraw -> k fp16
// ---------------------------------------------------------------------------
__global__ void rope_conv(const int* __restrict__ pos,
                          fp16* __restrict__ q, fp16* __restrict__ k)
{
    int t = blockIdx.x * 256 + threadIdx.x;
    const int TOT = BDIM * SEQ * (NH + 1) * HALF;
    if (t >= TOT) return;
    int i = t & (HALF - 1);
    int rest = t >> 7;
    int hh = rest % (NH + 1); rest /= (NH + 1);
    int s = rest % SEQ;
    int b = rest / SEQ;

    float p = (float)pos[b * SEQ + s];
    float freq = powf(10000.f, -(float)(2 * i) / (float)HD);
    float ang = p * freq;
    float sn, cs;
    sincosf(ang, &sn, &cs);

    if (hh < NH) {
        size_t base = ((size_t)(b * SEQ + s) * NH + hh) * HD;
        float x0 = g_qraw[base + i] * 0.0625f;
        float x1 = g_qraw[base + i + HALF] * 0.0625f;
        size_t ob = ((size_t)(b * NH + hh) * SEQ + s) * HD;
        q[ob + i]        = __float2half_rn(x0 * cs - x1 * sn);
        q[ob + i + HALF] = __float2half_rn(x1 * cs + x0 * sn);
    } else {
        size_t base = (size_t)(b * SEQ + s) * HD;
        float x0 = g_kraw[base + i];
        float x1 = g_kraw[base + i + HALF];
        k[base + i]        = __float2half_rn(x0 * cs - x1 * sn);
        k[base + i + HALF] = __float2half_rn(x1 * cs + x0 * sn);
    }
}

// ---------------------------------------------------------------------------
// Normalize: attn[row][j] = e[j] / rowsum[row] (f32 output), zero tail.
// ---------------------------------------------------------------------------
__global__ __launch_bounds__(256) void normalize_attn(
    const fp16* __restrict__ at, const float* __restrict__ rsum,
    float* __restrict__ attn)
{
    int row = blockIdx.x;
    int q = row & (SEQ - 1);
    float inv = 1.f / rsum[row];
    const fp16* re = at + (size_t)row * SEQ;
    float* ro = attn + (size_t)row * SEQ;
    int lim = ((q >> 7) + 1) << 7;
    int tid = threadIdx.x;

    for (int j = tid * 4; j < lim; j += 1024) {
        uint2 hv = *(const uint2*)(re + j);
        float2 a = __half22float2(*(__half2*)&hv.x);
        float2 b = __half22float2(*(__half2*)&hv.y);
        *(float4*)(ro + j) = make_float4(a.x * inv, a.y * inv, b.x * inv, b.y * inv);
    }
    for (int j = lim + tid * 4; j < SEQ; j += 1024)
        *(float4*)(ro + j) = make_float4(0.f, 0.f, 0.f, 0.f);
}

// ---------------------------------------------------------------------------
// Host launcher
// ---------------------------------------------------------------------------
extern "C" void kernel_launch(void* const* d_in, const int* in_sizes, int n_in,
                              void* d_out, int out_size)
{
    const float* hidden = (const float*)d_in[0];
    const float* Wq     = (const float*)d_in[1];
    const float* Wk     = (const float*)d_in[2];
    const float* Wv     = (const float*)d_in[3];
    const float* Wo     = (const float*)d_in[4];
    const int*   pos    = (const int*)d_in[6];

    float *qraw, *kraw, *attn_s, *rsum;
    fp16 *hid, *wqkv, *wo, *q, *k, *v, *at, *ah;

    cudaGetSymbolAddress((void**)&qraw, g_qraw);
    cudaGetSymbolAddress((void**)&kraw, g_kraw);
    cudaGetSymbolAddress((void**)&attn_s, g_attn_s);
    cudaGetSymbolAddress((void**)&rsum, g_rsum);
    cudaGetSymbolAddress((void**)&hid, g_hid);
    cudaGetSymbolAddress((void**)&wqkv, g_wqkv);
    cudaGetSymbolAddress((void**)&wo,  g_wo);
    cudaGetSymbolAddress((void**)&q,   g_q);
    cudaGetSymbolAddress((void**)&k,   g_k);
    cudaGetSymbolAddress((void**)&v,   g_v);
    cudaGetSymbolAddress((void**)&at,  g_at);
    cudaGetSymbolAddress((void**)&ah,  g_ah);

    float* out = (float*)d_out;
    const long long OUTE  = (long long)BDIM * SEQ * HID;
    const long long ATTNE = (long long)BDIM * NH * SEQ * SEQ;
    float* attn = ((long long)out_size >= OUTE + ATTNE) ? (out + OUTE) : attn_s;

    const int M = BDIM * SEQ;  // 4096

    const int AEL = BM * (BK + 8);            // 5120 elems
    const int BEL_NN = BK * (BN + 8);         // 4352 elems
    const int SM_NN1 = STAGES * (AEL + BEL_NN) * 2;        // 56832
    const int SM_NT1 = STAGES * (2 * AEL) * 2;             // 61440
    cudaFuncSetAttribute(gemm2p<false>, cudaFuncAttributeMaxDynamicSharedMemorySize, SM_NN1);
    cudaFuncSetAttribute(gemm2p<true>,  cudaFuncAttributeMaxDynamicSharedMemorySize, SM_NT1);

    // 1: conversions + rowsum zeroing
    conv_all<<<(CV4TOT + 255) / 256, 256>>>(hidden, Wq, Wk, Wv, Wo, hid, wqkv, wo, rsum);

    // 2: merged QKV projection (single-pass, N=2560)
    gemm2p<false><<<dim3(2560/BN, M/BM, 1), 256, SM_NN1>>>(
        hid, nullptr, wqkv, qraw, kraw, v, nullptr,
        HID, HID, 2560, HID, 1, 0,0,0,0,0,0, 0, 4);

    // 3: RoPE
    { int TOT = BDIM*SEQ*(NH+1)*HALF; rope_conv<<<(TOT+255)/256, 256>>>(pos, q, k); }

    // 4: scores = q @ k^T, fused exp + rowsum -> fp16 e-plane
    gemm2p<true><<<dim3(SEQ/BN, SEQ/BM, BDIM*NH), 256, SM_NT1>>>(
        q, nullptr, k, nullptr, nullptr, at, rsum,
        HD, HD, HD, SEQ,
        NH,
        (long long)NH*SEQ*HD, (long long)SEQ*HD,
        (long long)SEQ*HD, 0,
        (long long)NH*SEQ*SEQ, (long long)SEQ*SEQ,
        1, 6);

    // 5: normalize e-plane into the f32 attn output
    normalize_attn<<<BDIM*NH*SEQ, 256>>>(at, rsum, attn);

    // 6: PV (single-pass on unnormalized e), epilogue divides by rowsum
    gemm2p<false><<<dim3(HD/BN, SEQ/BM, BDIM*NH), 256, SM_NN1>>>(
        at, nullptr, v, nullptr, nullptr, ah, rsum,
        SEQ, SEQ, HD, NH*HD,
        NH,
        (long long)NH*SEQ*SEQ, (long long)SEQ*SEQ,
        (long long)SEQ*HD, 0,
        (long long)SEQ*NH*HD, (long long)HD,
        2, 5);

    // 7: out = ah @ Wo (single-pass)
    gemm2p<false><<<dim3(HID/BN, M/BM, 1), 256, SM_NN1>>>(
        ah, nullptr, wo, out, nullptr, nullptr, nullptr,
        NH*HD, NH*HD, HID, HID, 1, 0,0,0,0,0,0, 0, 0);
}